// round 8
// baseline (speedup 1.0000x reference)
#include <cuda_runtime.h>
#include <math.h>
#include <stdint.h>

// ---------------- problem constants ----------------
#define NB   2048
#define SQN  64
#define PCN  24
#define FDIM 16
#define HDIM 128
#define DDIM 256
#define TDIM 128
#define ADIM 4672
#define E_ADJ 420
#define E_OCC 24
#define E_ATT 40
#define E_DEF 40
#define E_REV 24
#define T512 512

// ---------------- scratch (static device globals: allocation-free) ----------------
__device__ float g_shared[NB * DDIM];  // 2 MB
__device__ float g_pt[NB * TDIM];      // 1 MB
__device__ float g_vt[NB * TDIM];      // 1 MB

// gelu via __expf (MUFU.EX2); rel err ~1e-6, far under 1e-3 budget.
__device__ __forceinline__ float gelu_f(float x) {
    float u = 0.7978845608028654f * x + 0.0356774081f * x * x * x;
    float au = fabsf(u);
    float e = __expf(-2.0f * au);
    float t = __fdividef(1.0f - e, 1.0f + e);
    t = copysignf(t, u);
    return 0.5f * x * (1.0f + t);
}

// ---------------- smem layout for board kernel (word offsets) ----------------
#define OFF_HSQ   0        // 64*128  = 8192
#define OFF_HPC   8192     // 24*128  = 3072
#define OFF_RADJ  11264    // 64*128  = 8192
#define OFF_AGGO  19456    // 64*128  = 8192
#define OFF_RATT  27648    // 24*128  = 3072
#define OFF_RDEF  30720    // 24*128  = 3072
#define OFF_RREV  33792    // 24*128  = 3072
#define OFF_POCC  36864    // 24*128  = 3072
#define OFF_WST   39936    // 128*128 = 16384
#define OFF_SACC  56320    // 256
#define OFF_EIDX  56576    // 548 ints
#define SMEM1_BYTES (56576*4 + 548*4)   // 228496 B

// ---- weight prefetch helpers: 16384-float tile, 512 threads, 8 float4 each ----
__device__ __forceinline__ void pf_load128(float4* pf, const float* W, int t) {
    const float4* W4 = (const float4*)W;
    #pragma unroll
    for (int i = 0; i < 8; i++) pf[i] = W4[t + i * T512];
}
// W_out is (128,256); load half hh (cols hh*128..+128) into 128x128 tile regs
__device__ __forceinline__ void pf_load_out(float4* pf, const float* W_out, int hh, int t) {
    const float4* W4 = (const float4*)W_out;
    #pragma unroll
    for (int i = 0; i < 8; i++) {
        int idx = t + i * T512;     // 0..4095 float4 of the 128x128 tile
        int k = idx >> 5;           // row
        int c = idx & 31;           // float4-col within half
        pf[i] = W4[k * 64 + hh * 32 + c];
    }
}
__device__ __forceinline__ void pf_store(float* wst, const float4* pf, int t) {
    float4* w4 = (float4*)wst;
    #pragma unroll
    for (int i = 0; i < 8; i++) w4[t + i * T512] = pf[i];
}

// ---- register-tiled GEMM fragments ----
// 64-row A (64x128) @ wst (128x128): thread tile 4 rows x 4 cols
__device__ __forceinline__ void gemm64(const float* __restrict__ A,
                                       const float* __restrict__ wst,
                                       float C[4][4], int rg, int c4) {
    #pragma unroll 4
    for (int k = 0; k < 128; k++) {
        float4 bv = *(const float4*)&wst[k * 128 + c4];
        #pragma unroll
        for (int i = 0; i < 4; i++) {
            float a = A[(rg * 4 + i) * 128 + k];
            C[i][0] += a * bv.x; C[i][1] += a * bv.y;
            C[i][2] += a * bv.z; C[i][3] += a * bv.w;
        }
    }
}
// 24-row A (24x128) @ wst (128x128): thread tile 3 rows x 2 cols
__device__ __forceinline__ void gemm24(const float* __restrict__ A,
                                       const float* __restrict__ wst,
                                       float C[3][2], int rg2, int c2) {
    #pragma unroll 4
    for (int k = 0; k < 128; k++) {
        float2 bv = *(const float2*)&wst[k * 128 + c2];
        #pragma unroll
        for (int i = 0; i < 3; i++) {
            float a = A[(rg2 * 3 + i) * 128 + k];
            C[i][0] += a * bv.x; C[i][1] += a * bv.y;
        }
    }
}

// ============================================================================
// Kernel 1: one CTA (512 thr) per board. Fully fused GNN -> g_shared[b][256].
// ============================================================================
__global__ void __launch_bounds__(T512, 1) board_kernel(
    const float* __restrict__ x_sq, const float* __restrict__ x_pc,
    const float* __restrict__ W_in_sq, const float* __restrict__ b_in_sq,
    const float* __restrict__ W_in_pc, const float* __restrict__ b_in_pc,
    const float* __restrict__ W_adj, const float* __restrict__ W_occ,
    const float* __restrict__ W_att, const float* __restrict__ W_def,
    const float* __restrict__ W_rev,
    const float* __restrict__ W_out, const float* __restrict__ b_out,
    const int* __restrict__ ei_adj, const int* __restrict__ ei_occ,
    const int* __restrict__ ei_att, const int* __restrict__ ei_def,
    const int* __restrict__ ei_rev)
{
    extern __shared__ float sm[];
    float* h_sq   = sm + OFF_HSQ;
    float* h_pc   = sm + OFF_HPC;
    float* rawAdj = sm + OFF_RADJ;
    float* aggO   = sm + OFF_AGGO;
    float* rawAtt = sm + OFF_RATT;
    float* rawDef = sm + OFF_RDEF;
    float* rawRev = sm + OFF_RREV;
    float* p_occ  = sm + OFF_POCC;
    float* wst    = sm + OFF_WST;
    float* sacc   = sm + OFF_SACC;
    int*   eidx   = (int*)(sm + OFF_EIDX);

    const int b = blockIdx.x;
    const int t = threadIdx.x;

    float4 pf[8];
    pf_load128(pf, W_adj, t);   // prefetch first weight tile immediately

    // ---- load edges, board-local, pack s | d<<8.
    // layout: adj[0,420) att[420,460) def[460,500) rev[500,524) occ[524,548)
    {
        const int ba = b * E_ADJ;
        for (int i = t; i < E_ADJ; i += T512) {
            int s = ei_adj[ba + i] - b * SQN;
            int d = ei_adj[NB * E_ADJ + ba + i] - b * SQN;
            eidx[i] = s | (d << 8);
        }
        const int bt = b * E_ATT;
        for (int i = t; i < E_ATT; i += T512) {
            int s  = ei_att[bt + i] - b * PCN;
            int d  = ei_att[NB * E_ATT + bt + i] - b * PCN;
            eidx[E_ADJ + i] = s | (d << 8);
            int s2 = ei_def[bt + i] - b * PCN;
            int d2 = ei_def[NB * E_DEF + bt + i] - b * PCN;
            eidx[E_ADJ + E_ATT + i] = s2 | (d2 << 8);
        }
        const int bo = b * E_OCC;
        for (int i = t; i < E_REV; i += T512) {
            int s = ei_rev[bo + i] - b * SQN;                  // src: square
            int d = ei_rev[NB * E_REV + bo + i] - b * PCN;     // dst: piece
            eidx[500 + i] = s | (d << 8);
            int so = ei_occ[bo + i] - b * PCN;                 // src: piece
            int dd = ei_occ[NB * E_OCC + bo + i] - b * SQN;    // dst: square
            eidx[524 + i] = so | (dd << 8);
        }
    }

    // ---- zero raw buffers (rawAdj..rawRev contiguous, 25600 words) + sacc ----
    {
        float4* r4 = (float4*)rawAdj;
        for (int i = t; i < 6400; i += T512) r4[i] = make_float4(0.f, 0.f, 0.f, 0.f);
        if (t < 256) sacc[t] = 0.f;
    }

    // ---- stage x tiles + input weights into wst (plain layout) ----
    float* xs  = wst;              // 64*16
    float* xp  = wst + 1024;       // 24*16
    float* wi1 = wst + 2048;       // 16*128
    float* wi2 = wst + 4096;       // 16*128
    for (int i = t; i < SQN * FDIM; i += T512) xs[i] = x_sq[b * SQN * FDIM + i];
    for (int i = t; i < PCN * FDIM; i += T512) xp[i] = x_pc[b * PCN * FDIM + i];
    for (int i = t; i < FDIM * HDIM; i += T512) { wi1[i] = W_in_sq[i]; wi2[i] = W_in_pc[i]; }
    __syncthreads();   // S1

    // ---- Phase 1: h = gelu(x @ W_in + b_in). 512 thr: c = t&127, q = t>>7 ----
    {
        const int c = t & 127;
        const int q = t >> 7;  // 0..3
        float wcol[16];
        #pragma unroll
        for (int k = 0; k < 16; k++) wcol[k] = wi1[k * 128 + c];
        float bias = b_in_sq[c];
        for (int r = q * 16; r < q * 16 + 16; r++) {
            float acc = bias;
            #pragma unroll
            for (int k = 0; k < 16; k++) acc += xs[r * 16 + k] * wcol[k];
            h_sq[r * 128 + c] = gelu_f(acc);
        }
        #pragma unroll
        for (int k = 0; k < 16; k++) wcol[k] = wi2[k * 128 + c];
        bias = b_in_pc[c];
        for (int r = q * 6; r < q * 6 + 6; r++) {
            float acc = bias;
            #pragma unroll
            for (int k = 0; k < 16; k++) acc += xp[r * 16 + k] * wcol[k];
            h_pc[r * 128 + c] = gelu_f(acc);
        }
    }
    __syncthreads();   // S2

    // ---- Phase 2: edge aggregation via smem atomics (fire-and-forget) ----
    {
        const int g = t >> 7;     // 0..3 edge-strided groups
        const int c = t & 127;
        for (int i = g; i < E_ADJ; i += 4) {
            int e = eidx[i];
            atomicAdd(&rawAdj[(e >> 8) * 128 + c], h_sq[(e & 255) * 128 + c]);
        }
        for (int i = g; i < E_ATT; i += 4) {
            int e = eidx[E_ADJ + i];
            atomicAdd(&rawAtt[(e >> 8) * 128 + c], h_pc[(e & 255) * 128 + c]);
        }
        for (int i = g; i < E_DEF; i += 4) {
            int e = eidx[E_ADJ + E_ATT + i];
            atomicAdd(&rawDef[(e >> 8) * 128 + c], h_pc[(e & 255) * 128 + c]);
        }
        for (int i = g; i < E_REV; i += 4) {
            int e = eidx[500 + i];
            atomicAdd(&rawRev[(e >> 8) * 128 + c], h_sq[(e & 255) * 128 + c]);
        }
    }
    __syncthreads();   // S3 (raw done; wst free)

    const int c4  = (t & 31) * 4;
    const int rg  = t >> 5;   // 0..15 (4-row groups)
    const int c2  = (t & 63) * 2;
    const int rg2 = t >> 6;   // 0..7 (3-row groups)

    pf_store(wst, pf, t);            // W_adj -> wst
    pf_load128(pf, W_occ, t);        // prefetch W_occ (overlaps next GEMM)
    __syncthreads();   // S4

    // ---- GEMM adj: C_adj = rawAdj @ W_adj ----
    float Cadj[4][4];
    #pragma unroll
    for (int i = 0; i < 4; i++)
        #pragma unroll
        for (int j = 0; j < 4; j++) Cadj[i][j] = 0.f;
    gemm64(rawAdj, wst, Cadj, rg, c4);
    __syncthreads();   // S5 (wst consumed)

    pf_store(wst, pf, t);            // W_occ
    pf_load128(pf, W_att, t);
    __syncthreads();   // S6

    // ---- GEMM occ (24 rows): p_occ = h_pc @ W_occ ----
    {
        float C[3][2] = {{0.f,0.f},{0.f,0.f},{0.f,0.f}};
        gemm24(h_pc, wst, C, rg2, c2);
        #pragma unroll
        for (int i = 0; i < 3; i++) {
            p_occ[(rg2 * 3 + i) * 128 + c2]     = C[i][0];
            p_occ[(rg2 * 3 + i) * 128 + c2 + 1] = C[i][1];
        }
    }
    __syncthreads();   // S7 (p_occ visible; wst consumed)

    pf_store(wst, pf, t);            // W_att
    pf_load128(pf, W_def, t);
    // scatter occ rows into aggO (24 edges, atomics)
    {
        const int g = t >> 7;
        const int c = t & 127;
        for (int i = g; i < E_OCC; i += 4) {
            int e = eidx[524 + i];
            atomicAdd(&aggO[(e >> 8) * 128 + c], p_occ[(e & 255) * 128 + c]);
        }
    }
    __syncthreads();   // S8 (aggO done; W_att ready)

    // ---- epilogue squares: h_sq = gelu(h_sq + C_adj + aggO) ----
    #pragma unroll
    for (int i = 0; i < 4; i++) {
        int r = rg * 4 + i;
        #pragma unroll
        for (int j = 0; j < 4; j++) {
            float v = h_sq[r * 128 + c4 + j] + Cadj[i][j] + aggO[r * 128 + c4 + j];
            h_sq[r * 128 + c4 + j] = gelu_f(v);
        }
    }

    // ---- piece GEMM chain: C_pc = rawAtt@W_att + rawDef@W_def + rawRev@W_rev ----
    float Cpc[3][2] = {{0.f,0.f},{0.f,0.f},{0.f,0.f}};
    gemm24(rawAtt, wst, Cpc, rg2, c2);
    __syncthreads();   // S9
    pf_store(wst, pf, t);            // W_def
    pf_load128(pf, W_rev, t);
    __syncthreads();   // S10
    gemm24(rawDef, wst, Cpc, rg2, c2);
    __syncthreads();   // S11
    pf_store(wst, pf, t);            // W_rev
    pf_load_out(pf, W_out, 0, t);    // prefetch W_out half0
    __syncthreads();   // S12
    gemm24(rawRev, wst, Cpc, rg2, c2);
    // epilogue pieces: h_pc = gelu(h_pc + C_pc)
    #pragma unroll
    for (int i = 0; i < 3; i++) {
        int r = rg2 * 3 + i;
        #pragma unroll
        for (int j = 0; j < 2; j++) {
            float v = h_pc[r * 128 + c2 + j] + Cpc[i][j];
            h_pc[r * 128 + c2 + j] = gelu_f(v);
        }
    }
    __syncthreads();   // S13 (h_sq/h_pc final; wst consumed)

    // ---- Phase 4: out = gelu(h2 @ W_out + b_out); board-mean into sacc ----
    #pragma unroll
    for (int hh = 0; hh < 2; hh++) {
        pf_store(wst, pf, t);        // W_out half hh
        if (hh == 0) pf_load_out(pf, W_out, 1, t);
        __syncthreads();
        // squares 64 rows
        {
            float C[4][4];
            #pragma unroll
            for (int i = 0; i < 4; i++)
                #pragma unroll
                for (int j = 0; j < 4; j++) C[i][j] = 0.f;
            gemm64(h_sq, wst, C, rg, c4);
            #pragma unroll
            for (int j = 0; j < 4; j++) {
                int cg = hh * 128 + c4 + j;
                float bo = b_out[cg];
                float s = 0.f;
                #pragma unroll
                for (int i = 0; i < 4; i++) s += gelu_f(C[i][j] + bo);
                atomicAdd(&sacc[cg], s * (1.0f / 64.0f));
            }
        }
        // pieces 24 rows
        {
            float C[3][2] = {{0.f,0.f},{0.f,0.f},{0.f,0.f}};
            gemm24(h_pc, wst, C, rg2, c2);
            #pragma unroll
            for (int j = 0; j < 2; j++) {
                int cg = hh * 128 + c2 + j;
                float bo = b_out[cg];
                float s = 0.f;
                #pragma unroll
                for (int i = 0; i < 3; i++) s += gelu_f(C[i][j] + bo);
                atomicAdd(&sacc[cg], s * (1.0f / 24.0f));
            }
        }
        __syncthreads();
    }
    if (t < 256) g_shared[b * DDIM + t] = sacc[t];
}

// ============================================================================
// Kernel 2: pt = gelu(shared @ W_pt + b_pt), vt = gelu(shared @ W_vt + b_vt)
// ============================================================================
#define SMEM2_BYTES ((4096 + 32768) * 4)
__global__ void __launch_bounds__(256) heads_kernel(
    const float* __restrict__ W_pt, const float* __restrict__ b_pt,
    const float* __restrict__ W_vt, const float* __restrict__ b_vt)
{
    extern __shared__ float sm[];
    float* At = sm;          // 16*256
    float* Bt = sm + 4096;   // 256*128
    const int t = threadIdx.x;
    const int r0 = blockIdx.x * 16;

    for (int i = t; i < 16 * 256; i += 256) At[i] = g_shared[r0 * 256 + i];

    const int c4 = (t & 31) * 4;
    const int rg = t >> 5;

    #pragma unroll
    for (int w = 0; w < 2; w++) {
        __syncthreads();
        const float* W  = w ? W_vt : W_pt;
        const float* bb = w ? b_vt : b_pt;
        float* outp     = w ? g_vt : g_pt;
        for (int i = t; i < 256 * 128; i += 256) Bt[i] = W[i];
        __syncthreads();
        float C[2][4] = {{0.f, 0.f, 0.f, 0.f}, {0.f, 0.f, 0.f, 0.f}};
        #pragma unroll 4
        for (int k = 0; k < 256; k++) {
            float4 bv = *(const float4*)&Bt[k * 128 + c4];
            float a0 = At[(rg * 2) * 256 + k];
            float a1 = At[(rg * 2 + 1) * 256 + k];
            C[0][0] += a0 * bv.x; C[0][1] += a0 * bv.y; C[0][2] += a0 * bv.z; C[0][3] += a0 * bv.w;
            C[1][0] += a1 * bv.x; C[1][1] += a1 * bv.y; C[1][2] += a1 * bv.z; C[1][3] += a1 * bv.w;
        }
        #pragma unroll
        for (int i = 0; i < 2; i++) {
            int r = r0 + rg * 2 + i;
            float4 o;
            o.x = gelu_f(C[i][0] + bb[c4 + 0]);
            o.y = gelu_f(C[i][1] + bb[c4 + 1]);
            o.z = gelu_f(C[i][2] + bb[c4 + 2]);
            o.w = gelu_f(C[i][3] + bb[c4 + 3]);
            *(float4*)&outp[r * 128 + c4] = o;
        }
    }
}

// ============================================================================
// Kernel 3: policy = pt @ W_ph + b_ph  (2048 x 4672, K=128)
// ============================================================================
#define SMEM3_BYTES ((8192 + 16384) * 4)
__global__ void __launch_bounds__(256) policy_kernel(
    const float* __restrict__ W_ph, const float* __restrict__ b_ph,
    float* __restrict__ out)
{
    extern __shared__ float sm[];
    float* At = sm;          // 64*128
    float* Bt = sm + 8192;   // 128*128
    const int t = threadIdx.x;
    const int rb = blockIdx.y * 64;
    const int cb = blockIdx.x * 128;

    for (int i = t; i < 64 * 128; i += 256) At[i] = g_pt[rb * 128 + i];
    for (int m = t; m < 128 * 128; m += 256) {
        int k = m >> 7, j = m & 127;
        int col = cb + j;
        Bt[m] = (col < ADIM) ? W_ph[k * ADIM + col] : 0.f;
    }
    __syncthreads();

    const int c4 = (t & 31) * 4;
    const int rg = t >> 5;
    float C[8][4];
    #pragma unroll
    for (int i = 0; i < 8; i++)
        #pragma unroll
        for (int j = 0; j < 4; j++) C[i][j] = 0.f;

    #pragma unroll 4
    for (int k = 0; k < 128; k++) {
        float4 bv = *(const float4*)&Bt[k * 128 + c4];
        #pragma unroll
        for (int i = 0; i < 8; i++) {
            float a = At[(rg * 8 + i) * 128 + k];
            C[i][0] += a * bv.x; C[i][1] += a * bv.y;
            C[i][2] += a * bv.z; C[i][3] += a * bv.w;
        }
    }
    #pragma unroll
    for (int i = 0; i < 8; i++) {
        int r = rb + rg * 8 + i;
        #pragma unroll
        for (int j = 0; j < 4; j++) {
            int col = cb + c4 + j;
            if (col < ADIM) out[r * ADIM + col] = C[i][j] + b_ph[col];
        }
    }
}

// ============================================================================
// Kernel 4: value = tanh(vt @ W_vh + b_vh)  (2048 x 1)
// ============================================================================
__global__ void __launch_bounds__(256) value_kernel(
    const float* __restrict__ W_vh, const float* __restrict__ b_vh,
    float* __restrict__ out)
{
    int r = blockIdx.x * 8 + (threadIdx.x >> 5);
    int lane = threadIdx.x & 31;
    float acc = 0.f;
    #pragma unroll
    for (int q = 0; q < 4; q++)
        acc += g_vt[r * 128 + q * 32 + lane] * W_vh[q * 32 + lane];
    #pragma unroll
    for (int o = 16; o; o >>= 1) acc += __shfl_xor_sync(0xffffffffu, acc, o);
    if (lane == 0) out[(size_t)NB * ADIM + r] = tanhf(acc + b_vh[0]);
}

// ============================================================================
extern "C" void kernel_launch(void* const* d_in, const int* in_sizes, int n_in,
                              void* d_out, int out_size) {
    (void)in_sizes; (void)n_in; (void)out_size;
    const float* x_sq    = (const float*)d_in[0];
    const float* x_pc    = (const float*)d_in[1];
    const float* W_in_sq = (const float*)d_in[2];
    const float* b_in_sq = (const float*)d_in[3];
    const float* W_in_pc = (const float*)d_in[4];
    const float* b_in_pc = (const float*)d_in[5];
    const float* W_adj   = (const float*)d_in[6];
    const float* W_occ   = (const float*)d_in[7];
    const float* W_att   = (const float*)d_in[8];
    const float* W_def   = (const float*)d_in[9];
    const float* W_rev   = (const float*)d_in[10];
    const float* W_out   = (const float*)d_in[11];
    const float* b_out   = (const float*)d_in[12];
    const float* W_pt    = (const float*)d_in[13];
    const float* b_pt    = (const float*)d_in[14];
    const float* W_vt    = (const float*)d_in[15];
    const float* b_vt    = (const float*)d_in[16];
    const float* W_ph    = (const float*)d_in[17];
    const float* b_ph    = (const float*)d_in[18];
    const float* W_vh    = (const float*)d_in[19];
    const float* b_vh    = (const float*)d_in[20];
    const int* ei_adj    = (const int*)d_in[21];
    const int* ei_occ    = (const int*)d_in[22];
    const int* ei_att    = (const int*)d_in[23];
    const int* ei_def    = (const int*)d_in[24];
    const int* ei_rev    = (const int*)d_in[25];
    float* out = (float*)d_out;

    cudaFuncSetAttribute(board_kernel,  cudaFuncAttributeMaxDynamicSharedMemorySize, SMEM1_BYTES);
    cudaFuncSetAttribute(heads_kernel,  cudaFuncAttributeMaxDynamicSharedMemorySize, SMEM2_BYTES);
    cudaFuncSetAttribute(policy_kernel, cudaFuncAttributeMaxDynamicSharedMemorySize, SMEM3_BYTES);

    board_kernel<<<NB, T512, SMEM1_BYTES>>>(
        x_sq, x_pc, W_in_sq, b_in_sq, W_in_pc, b_in_pc,
        W_adj, W_occ, W_att, W_def, W_rev, W_out, b_out,
        ei_adj, ei_occ, ei_att, ei_def, ei_rev);

    heads_kernel<<<NB / 16, 256, SMEM2_BYTES>>>(W_pt, b_pt, W_vt, b_vt);

    policy_kernel<<<dim3((ADIM + 127) / 128, NB / 64), 256, SMEM3_BYTES>>>(W_ph, b_ph, out);

    value_kernel<<<NB / 8, 256>>>(W_vh, b_vh, out);
}

// round 9
// speedup vs baseline: 1.0405x; 1.0405x over previous
#include <cuda_runtime.h>
#include <math.h>
#include <stdint.h>

#define NB   2048
#define SQN  64
#define PCN  24
#define FDIM 16
#define HDIM 128
#define DDIM 256
#define TDIM 128
#define ADIM 4672
#define E_ADJ 420
#define E_OCC 24
#define E_ATT 40
#define E_DEF 40
#define E_REV 24
#define T512 512

__device__ float g_shared[NB * DDIM];
__device__ float g_pt[NB * TDIM];
__device__ float g_vt[NB * TDIM];

__device__ __forceinline__ float gelu_f(float x) {
    float u = 0.7978845608028654f * x + 0.0356774081f * x * x * x;
    float au = fabsf(u);
    float e = __expf(-2.0f * au);
    float t = __fdividef(1.0f - e, 1.0f + e);
    t = copysignf(t, u);
    return 0.5f * x * (1.0f + t);
}

#define OFF_HSQ   0
#define OFF_HPC   8192
#define OFF_RADJ  11264
#define OFF_AGGO  19456
#define OFF_RATT  27648
#define OFF_RDEF  30720
#define OFF_RREV  33792
#define OFF_POCC  36864
#define OFF_WST   39936
#define OFF_SACC  56320
#define OFF_EIDX  56576
#define SMEM1_BYTES (56576*4 + 548*4)

__device__ __forceinline__ void pf_load128(float4* pf, const float* W, int t) {
    const float4* W4 = (const float4*)W;
    #pragma unroll
    for (int i = 0; i < 8; i++) pf[i] = W4[t + i * T512];
}
__device__ __forceinline__ void pf_load_out(float4* pf, const float* W_out, int hh, int t) {
    const float4* W4 = (const float4*)W_out;
    #pragma unroll
    for (int i = 0; i < 8; i++) {
        int idx = t + i * T512;
        int k = idx >> 5;
        int c = idx & 31;
        pf[i] = W4[k * 64 + hh * 32 + c];
    }
}
__device__ __forceinline__ void pf_store(float* wst, const float4* pf, int t) {
    float4* w4 = (float4*)wst;
    #pragma unroll
    for (int i = 0; i < 8; i++) w4[t + i * T512] = pf[i];
}

__device__ __forceinline__ float sel4(float4 v, int kk) {
    return kk == 0 ? v.x : kk == 1 ? v.y : kk == 2 ? v.z : v.w;
}

// 64x128 @ 128x128, thread tile 4x4, k-vectorized A broadcasts (LDS.128)
__device__ __forceinline__ void gemm64(const float* __restrict__ A,
                                       const float* __restrict__ wst,
                                       float C[4][4], int rg, int c4) {
    #pragma unroll 2
    for (int k = 0; k < 128; k += 4) {
        float4 a[4];
        #pragma unroll
        for (int i = 0; i < 4; i++) a[i] = *(const float4*)&A[(rg * 4 + i) * 128 + k];
        #pragma unroll
        for (int kk = 0; kk < 4; kk++) {
            float4 bv = *(const float4*)&wst[(k + kk) * 128 + c4];
            #pragma unroll
            for (int i = 0; i < 4; i++) {
                float av = sel4(a[i], kk);
                C[i][0] += av * bv.x; C[i][1] += av * bv.y;
                C[i][2] += av * bv.z; C[i][3] += av * bv.w;
            }
        }
    }
}
// 24x128 @ 128x128, thread tile 3x2, k-vectorized A broadcasts
__device__ __forceinline__ void gemm24(const float* __restrict__ A,
                                       const float* __restrict__ wst,
                                       float C[3][2], int rg2, int c2) {
    #pragma unroll 2
    for (int k = 0; k < 128; k += 4) {
        float4 a[3];
        #pragma unroll
        for (int i = 0; i < 3; i++) a[i] = *(const float4*)&A[(rg2 * 3 + i) * 128 + k];
        #pragma unroll
        for (int kk = 0; kk < 4; kk++) {
            float2 bv = *(const float2*)&wst[(k + kk) * 128 + c2];
            #pragma unroll
            for (int i = 0; i < 3; i++) {
                float av = sel4(a[i], kk);
                C[i][0] += av * bv.x; C[i][1] += av * bv.y;
            }
        }
    }
}

__global__ void __launch_bounds__(T512, 1) board_kernel(
    const float* __restrict__ x_sq, const float* __restrict__ x_pc,
    const float* __restrict__ W_in_sq, const float* __restrict__ b_in_sq,
    const float* __restrict__ W_in_pc, const float* __restrict__ b_in_pc,
    const float* __restrict__ W_adj, const float* __restrict__ W_occ,
    const float* __restrict__ W_att, const float* __restrict__ W_def,
    const float* __restrict__ W_rev,
    const float* __restrict__ W_out, const float* __restrict__ b_out,
    const int* __restrict__ ei_adj, const int* __restrict__ ei_occ,
    const int* __restrict__ ei_att, const int* __restrict__ ei_def,
    const int* __restrict__ ei_rev)
{
    extern __shared__ float sm[];
    float* h_sq   = sm + OFF_HSQ;
    float* h_pc   = sm + OFF_HPC;
    float* rawAdj = sm + OFF_RADJ;
    float* aggO   = sm + OFF_AGGO;
    float* rawAtt = sm + OFF_RATT;
    float* rawDef = sm + OFF_RDEF;
    float* rawRev = sm + OFF_RREV;
    float* p_occ  = sm + OFF_POCC;
    float* wst    = sm + OFF_WST;
    float* sacc   = sm + OFF_SACC;
    int*   eidx   = (int*)(sm + OFF_EIDX);

    const int b = blockIdx.x;
    const int t = threadIdx.x;

    float4 pf[8];
    pf_load128(pf, W_adj, t);

    {
        const int ba = b * E_ADJ;
        for (int i = t; i < E_ADJ; i += T512) {
            int s = ei_adj[ba + i] - b * SQN;
            int d = ei_adj[NB * E_ADJ + ba + i] - b * SQN;
            eidx[i] = s | (d << 8);
        }
        const int bt = b * E_ATT;
        for (int i = t; i < E_ATT; i += T512) {
            int s  = ei_att[bt + i] - b * PCN;
            int d  = ei_att[NB * E_ATT + bt + i] - b * PCN;
            eidx[E_ADJ + i] = s | (d << 8);
            int s2 = ei_def[bt + i] - b * PCN;
            int d2 = ei_def[NB * E_DEF + bt + i] - b * PCN;
            eidx[E_ADJ + E_ATT + i] = s2 | (d2 << 8);
        }
        const int bo = b * E_OCC;
        for (int i = t; i < E_REV; i += T512) {
            int s = ei_rev[bo + i] - b * SQN;
            int d = ei_rev[NB * E_REV + bo + i] - b * PCN;
            eidx[500 + i] = s | (d << 8);
            int so = ei_occ[bo + i] - b * PCN;
            int dd = ei_occ[NB * E_OCC + bo + i] - b * SQN;
            eidx[524 + i] = so | (dd << 8);
        }
    }

    {
        float4* r4 = (float4*)rawAdj;
        for (int i = t; i < 6400; i += T512) r4[i] = make_float4(0.f, 0.f, 0.f, 0.f);
        if (t < 256) sacc[t] = 0.f;
    }

    float* xs  = wst;
    float* xp  = wst + 1024;
    float* wi1 = wst + 2048;
    float* wi2 = wst + 4096;
    for (int i = t; i < SQN * FDIM; i += T512) xs[i] = x_sq[b * SQN * FDIM + i];
    for (int i = t; i < PCN * FDIM; i += T512) xp[i] = x_pc[b * PCN * FDIM + i];
    for (int i = t; i < FDIM * HDIM; i += T512) { wi1[i] = W_in_sq[i]; wi2[i] = W_in_pc[i]; }
    __syncthreads();

    {
        const int c = t & 127;
        const int q = t >> 7;
        float wcol[16];
        #pragma unroll
        for (int k = 0; k < 16; k++) wcol[k] = wi1[k * 128 + c];
        float bias = b_in_sq[c];
        for (int r = q * 16; r < q * 16 + 16; r++) {
            float acc = bias;
            #pragma unroll
            for (int k = 0; k < 16; k++) acc += xs[r * 16 + k] * wcol[k];
            h_sq[r * 128 + c] = gelu_f(acc);
        }
        #pragma unroll
        for (int k = 0; k < 16; k++) wcol[k] = wi2[k * 128 + c];
        bias = b_in_pc[c];
        for (int r = q * 6; r < q * 6 + 6; r++) {
            float acc = bias;
            #pragma unroll
            for (int k = 0; k < 16; k++) acc += xp[r * 16 + k] * wcol[k];
            h_pc[r * 128 + c] = gelu_f(acc);
        }
    }
    __syncthreads();

    {
        const int g = t >> 7;
        const int c = t & 127;
        for (int i = g; i < E_ADJ; i += 4) {
            int e = eidx[i];
            atomicAdd(&rawAdj[(e >> 8) * 128 + c], h_sq[(e & 255) * 128 + c]);
        }
        for (int i = g; i < E_ATT; i += 4) {
            int e = eidx[E_ADJ + i];
            atomicAdd(&rawAtt[(e >> 8) * 128 + c], h_pc[(e & 255) * 128 + c]);
        }
        for (int i = g; i < E_DEF; i += 4) {
            int e = eidx[E_ADJ + E_ATT + i];
            atomicAdd(&rawDef[(e >> 8) * 128 + c], h_pc[(e & 255) * 128 + c]);
        }
        for (int i = g; i < E_REV; i += 4) {
            int e = eidx[500 + i];
            atomicAdd(&rawRev[(e >> 8) * 128 + c], h_sq[(e & 255) * 128 + c]);
        }
    }
    __syncthreads();

    const int c4  = (t & 31) * 4;
    const int rg  = t >> 5;
    const int c2  = (t & 63) * 2;
    const int rg2 = t >> 6;

    pf_store(wst, pf, t);
    pf_load128(pf, W_occ, t);
    __syncthreads();

    float Cadj[4][4];
    #pragma unroll
    for (int i = 0; i < 4; i++)
        #pragma unroll
        for (int j = 0; j < 4; j++) Cadj[i][j] = 0.f;
    gemm64(rawAdj, wst, Cadj, rg, c4);
    __syncthreads();

    pf_store(wst, pf, t);
    pf_load128(pf, W_att, t);
    __syncthreads();

    {
        float C[3][2] = {{0.f,0.f},{0.f,0.f},{0.f,0.f}};
        gemm24(h_pc, wst, C, rg2, c2);
        #pragma unroll
        for (int i = 0; i < 3; i++) {
            p_occ[(rg2 * 3 + i) * 128 + c2]     = C[i][0];
            p_occ[(rg2 * 3 + i) * 128 + c2 + 1] = C[i][1];
        }
    }
    __syncthreads();

    pf_store(wst, pf, t);
    pf_load128(pf, W_def, t);
    {
        const int g = t >> 7;
        const int c = t & 127;
        for (int i = g; i < E_OCC; i += 4) {
            int e = eidx[524 + i];
            atomicAdd(&aggO[(e >> 8) * 128 + c], p_occ[(e & 255) * 128 + c]);
        }
    }
    __syncthreads();

    #pragma unroll
    for (int i = 0; i < 4; i++) {
        int r = rg * 4 + i;
        #pragma unroll
        for (int j = 0; j < 4; j++) {
            float v = h_sq[r * 128 + c4 + j] + Cadj[i][j] + aggO[r * 128 + c4 + j];
            h_sq[r * 128 + c4 + j] = gelu_f(v);
        }
    }

    float Cpc[3][2] = {{0.f,0.f},{0.f,0.f},{0.f,0.f}};
    gemm24(rawAtt, wst, Cpc, rg2, c2);
    __syncthreads();
    pf_store(wst, pf, t);
    pf_load128(pf, W_rev, t);
    __syncthreads();
    gemm24(rawDef, wst, Cpc, rg2, c2);
    __syncthreads();
    pf_store(wst, pf, t);
    pf_load_out(pf, W_out, 0, t);
    __syncthreads();
    gemm24(rawRev, wst, Cpc, rg2, c2);
    #pragma unroll
    for (int i = 0; i < 3; i++) {
        int r = rg2 * 3 + i;
        #pragma unroll
        for (int j = 0; j < 2; j++) {
            float v = h_pc[r * 128 + c2 + j] + Cpc[i][j];
            h_pc[r * 128 + c2 + j] = gelu_f(v);
        }
    }
    __syncthreads();

    #pragma unroll
    for (int hh = 0; hh < 2; hh++) {
        pf_store(wst, pf, t);
        if (hh == 0) pf_load_out(pf, W_out, 1, t);
        __syncthreads();
        {
            float C[4][4];
            #pragma unroll
            for (int i = 0; i < 4; i++)
                #pragma unroll
                for (int j = 0; j < 4; j++) C[i][j] = 0.f;
            gemm64(h_sq, wst, C, rg, c4);
            #pragma unroll
            for (int j = 0; j < 4; j++) {
                int cg = hh * 128 + c4 + j;
                float bo = b_out[cg];
                float s = 0.f;
                #pragma unroll
                for (int i = 0; i < 4; i++) s += gelu_f(C[i][j] + bo);
                atomicAdd(&sacc[cg], s * (1.0f / 64.0f));
            }
        }
        {
            float C[3][2] = {{0.f,0.f},{0.f,0.f},{0.f,0.f}};
            gemm24(h_pc, wst, C, rg2, c2);
            #pragma unroll
            for (int j = 0; j < 2; j++) {
                int cg = hh * 128 + c2 + j;
                float bo = b_out[cg];
                float s = 0.f;
                #pragma unroll
                for (int i = 0; i < 3; i++) s += gelu_f(C[i][j] + bo);
                atomicAdd(&sacc[cg], s * (1.0f / 24.0f));
            }
        }
        __syncthreads();
    }
    if (t < 256) g_shared[b * DDIM + t] = sacc[t];
}

#define SMEM2_BYTES ((4096 + 32768) * 4)
__global__ void __launch_bounds__(256) heads_kernel(
    const float* __restrict__ W_pt, const float* __restrict__ b_pt,
    const float* __restrict__ W_vt, const float* __restrict__ b_vt)
{
    extern __shared__ float sm[];
    float* At = sm;
    float* Bt = sm + 4096;
    const int t = threadIdx.x;
    const int r0 = blockIdx.x * 16;

    for (int i = t; i < 16 * 256; i += 256) At[i] = g_shared[r0 * 256 + i];

    const int c4 = (t & 31) * 4;
    const int rg = t >> 5;

    #pragma unroll
    for (int w = 0; w < 2; w++) {
        __syncthreads();
        const float* W  = w ? W_vt : W_pt;
        const float* bb = w ? b_vt : b_pt;
        float* outp     = w ? g_vt : g_pt;
        for (int i = t; i < 256 * 128; i += 256) Bt[i] = W[i];
        __syncthreads();
        float C[2][4] = {{0.f, 0.f, 0.f, 0.f}, {0.f, 0.f, 0.f, 0.f}};
        #pragma unroll 2
        for (int k = 0; k < 256; k += 4) {
            float4 a0 = *(const float4*)&At[(rg * 2) * 256 + k];
            float4 a1 = *(const float4*)&At[(rg * 2 + 1) * 256 + k];
            #pragma unroll
            for (int kk = 0; kk < 4; kk++) {
                float4 bv = *(const float4*)&Bt[(k + kk) * 128 + c4];
                float v0 = sel4(a0, kk), v1 = sel4(a1, kk);
                C[0][0] += v0 * bv.x; C[0][1] += v0 * bv.y; C[0][2] += v0 * bv.z; C[0][3] += v0 * bv.w;
                C[1][0] += v1 * bv.x; C[1][1] += v1 * bv.y; C[1][2] += v1 * bv.z; C[1][3] += v1 * bv.w;
            }
        }
        #pragma unroll
        for (int i = 0; i < 2; i++) {
            int r = r0 + rg * 2 + i;
            float4 o;
            o.x = gelu_f(C[i][0] + bb[c4 + 0]);
            o.y = gelu_f(C[i][1] + bb[c4 + 1]);
            o.z = gelu_f(C[i][2] + bb[c4 + 2]);
            o.w = gelu_f(C[i][3] + bb[c4 + 3]);
            *(float4*)&outp[r * 128 + c4] = o;
        }
    }
}

#define SMEM3_BYTES ((8192 + 16384) * 4)
__global__ void __launch_bounds__(256) policy_kernel(
    const float* __restrict__ W_ph, const float* __restrict__ b_ph,
    float* __restrict__ out)
{
    extern __shared__ float sm[];
    float* At = sm;
    float* Bt = sm + 8192;
    const int t = threadIdx.x;
    const int rb = blockIdx.y * 64;
    const int cb = blockIdx.x * 128;

    for (int i = t; i < 64 * 128; i += 256) At[i] = g_pt[rb * 128 + i];
    for (int m = t; m < 128 * 128; m += 256) {
        int k = m >> 7, j = m & 127;
        int col = cb + j;
        Bt[m] = (col < ADIM) ? W_ph[k * ADIM + col] : 0.f;
    }
    __syncthreads();

    const int c4 = (t & 31) * 4;
    const int rg = t >> 5;
    float C[8][4];
    #pragma unroll
    for (int i = 0; i < 8; i++)
        #pragma unroll
        for (int j = 0; j < 4; j++) C[i][j] = 0.f;

    #pragma unroll 2
    for (int k = 0; k < 128; k += 4) {
        float4 a[8];
        #pragma unroll
        for (int i = 0; i < 8; i++) a[i] = *(const float4*)&At[(rg * 8 + i) * 128 + k];
        #pragma unroll
        for (int kk = 0; kk < 4; kk++) {
            float4 bv = *(const float4*)&Bt[(k + kk) * 128 + c4];
            #pragma unroll
            for (int i = 0; i < 8; i++) {
                float av = sel4(a[i], kk);
                C[i][0] += av * bv.x; C[i][1] += av * bv.y;
                C[i][2] += av * bv.z; C[i][3] += av * bv.w;
            }
        }
    }
    #pragma unroll
    for (int i = 0; i < 8; i++) {
        int r = rb + rg * 8 + i;
        #pragma unroll
        for (int j = 0; j < 4; j++) {
            int col = cb + c4 + j;
            if (col < ADIM) out[r * ADIM + col] = C[i][j] + b_ph[col];
        }
    }
}

__global__ void __launch_bounds__(256) value_kernel(
    const float* __restrict__ W_vh, const float* __restrict__ b_vh,
    float* __restrict__ out)
{
    int r = blockIdx.x * 8 + (threadIdx.x >> 5);
    int lane = threadIdx.x & 31;
    float acc = 0.f;
    #pragma unroll
    for (int q = 0; q < 4; q++)
        acc += g_vt[r * 128 + q * 32 + lane] * W_vh[q * 32 + lane];
    #pragma unroll
    for (int o = 16; o; o >>= 1) acc += __shfl_xor_sync(0xffffffffu, acc, o);
    if (lane == 0) out[(size_t)NB * ADIM + r] = tanhf(acc + b_vh[0]);
}

extern "C" void kernel_launch(void* const* d_in, const int* in_sizes, int n_in,
                              void* d_out, int out_size) {
    (void)in_sizes; (void)n_in; (void)out_size;
    const float* x_sq    = (const float*)d_in[0];
    const float* x_pc    = (const float*)d_in[1];
    const float* W_in_sq = (const float*)d_in[2];
    const float* b_in_sq = (const float*)d_in[3];
    const float* W_in_pc = (const float*)d_in[4];
    const float* b_in_pc = (const float*)d_in[5];
    const float* W_adj   = (const float*)d_in[6];
    const float* W_occ   = (const float*)d_in[7];
    const float* W_att   = (const float*)d_in[8];
    const float* W_def   = (const float*)d_in[9];
    const float* W_rev   = (const float*)d_in[10];
    const float* W_out   = (const float*)d_in[11];
    const float* b_out   = (const float*)d_in[12];
    const float* W_pt    = (const float*)d_in[13];
    const float* b_pt    = (const float*)d_in[14];
    const float* W_vt    = (const float*)d_in[15];
    const float* b_vt    = (const float*)d_in[16];
    const float* W_ph    = (const float*)d_in[17];
    const float* b_ph    = (const float*)d_in[18];
    const float* W_vh    = (const float*)d_in[19];
    const float* b_vh    = (const float*)d_in[20];
    const int* ei_adj    = (const int*)d_in[21];
    const int* ei_occ    = (const int*)d_in[22];
    const int* ei_att    = (const int*)d_in[23];
    const int* ei_def    = (const int*)d_in[24];
    const int* ei_rev    = (const int*)d_in[25];
    float* out = (float*)d_out;

    cudaFuncSetAttribute(board_kernel,  cudaFuncAttributeMaxDynamicSharedMemorySize, SMEM1_BYTES);
    cudaFuncSetAttribute(heads_kernel,  cudaFuncAttributeMaxDynamicSharedMemorySize, SMEM2_BYTES);
    cudaFuncSetAttribute(policy_kernel, cudaFuncAttributeMaxDynamicSharedMemorySize, SMEM3_BYTES);

    board_kernel<<<NB, T512, SMEM1_BYTES>>>(
        x_sq, x_pc, W_in_sq, b_in_sq, W_in_pc, b_in_pc,
        W_adj, W_occ, W_att, W_def, W_rev, W_out, b_out,
        ei_adj, ei_occ, ei_att, ei_def, ei_rev);

    heads_kernel<<<NB / 16, 256, SMEM2_BYTES>>>(W_pt, b_pt, W_vt, b_vt);

    policy_kernel<<<dim3((ADIM + 127) / 128, NB / 64), 256, SMEM3_BYTES>>>(W_ph, b_ph, out);

    value_kernel<<<NB / 8, 256>>>(W_vh, b_vh, out);
}

// round 11
// speedup vs baseline: 1.1482x; 1.1036x over previous
#include <cuda_runtime.h>
#include <cuda_bf16.h>
#include <math.h>
#include <stdint.h>

#define NB   2048
#define SQN  64
#define PCN  24
#define FDIM 16
#define HDIM 128
#define DDIM 256
#define TDIM 128
#define ADIM 4672
#define E_ADJ 420
#define E_OCC 24
#define E_ATT 40
#define E_DEF 40
#define E_REV 24
#define T512 512
#define NSQT 1024
#define NPCT 384

__device__ float g_shared[NB * DDIM];
__device__ float g_pt[NB * TDIM];
__device__ float g_vt[NB * TDIM];
__device__ float g_h2sq[NB * SQN * HDIM];            // 64 MB
__device__ float g_h2pc[NB * PCN * HDIM];            // 24 MB
__device__ __nv_bfloat16 g_Bt[2 * 2 * 128 * 128];    // W_out^T bf16 [nh][hi/lo][n][k]

__device__ __forceinline__ float gelu_f(float x) {
    float u = 0.7978845608028654f * x + 0.0356774081f * x * x * x;
    float au = fabsf(u);
    float e = __expf(-2.0f * au);
    float t = __fdividef(1.0f - e, 1.0f + e);
    t = copysignf(t, u);
    return 0.5f * x * (1.0f + t);
}

__device__ __forceinline__ void mma_bf16(float c[4], uint32_t a0, uint32_t a1,
                                         uint32_t a2, uint32_t a3,
                                         uint32_t b0, uint32_t b1) {
    asm volatile(
        "mma.sync.aligned.m16n8k16.row.col.f32.bf16.bf16.f32 "
        "{%0,%1,%2,%3}, {%4,%5,%6,%7}, {%8,%9}, {%0,%1,%2,%3};"
        : "+f"(c[0]), "+f"(c[1]), "+f"(c[2]), "+f"(c[3])
        : "r"(a0), "r"(a1), "r"(a2), "r"(a3), "r"(b0), "r"(b1));
}

// ============================================================================
// prep: Bt[nh][hi/lo][n][k] = split(W_out[k][nh*128+n]); zero g_shared
// ============================================================================
__global__ void __launch_bounds__(256) prep_kernel(const float* __restrict__ W_out) {
    int tid = blockIdx.x * 256 + threadIdx.x;
    int stride = gridDim.x * 256;
    for (int i = tid; i < NB * DDIM; i += stride) g_shared[i] = 0.f;
    for (int i = tid; i < 2 * 128 * 128; i += stride) {
        int nh = i >> 14;
        int rem = i & 16383;
        int n = rem >> 7, k = rem & 127;
        float v = W_out[k * DDIM + nh * 128 + n];
        __nv_bfloat16 hi = __float2bfloat16(v);
        __nv_bfloat16 lo = __float2bfloat16(v - __bfloat162float(hi));
        g_Bt[((nh * 2 + 0) * 128 + n) * 128 + k] = hi;
        g_Bt[((nh * 2 + 1) * 128 + n) * 128 + k] = lo;
    }
}

// ============================================================================
// outgemm: D(128x128) = h2 @ W_out[nh] via mma.sync bf16 3-pass hi/lo
// grid 2816 x 256 thr; mt = bx>>1, nh = bx&1. Epilogue: bias+gelu+board-mean.
// ============================================================================
#define PADK 136
#define TILEB (128 * PADK * 2)      /* 34816 bytes per bf16 tile */
#define OG_AHI 0
#define OG_ALO TILEB
#define OG_BHI (2 * TILEB)
#define OG_BLO (3 * TILEB)
#define OG_SMEM (4 * TILEB)
#define SCRP 132

__global__ void __launch_bounds__(256, 1) outgemm_kernel(const float* __restrict__ b_out) {
    extern __shared__ uint8_t smraw[];
    __nv_bfloat16* Ahi = (__nv_bfloat16*)(smraw + OG_AHI);
    __nv_bfloat16* Alo = (__nv_bfloat16*)(smraw + OG_ALO);
    __nv_bfloat16* Bhi = (__nv_bfloat16*)(smraw + OG_BHI);
    __nv_bfloat16* Blo = (__nv_bfloat16*)(smraw + OG_BLO);

    const int t = threadIdx.x;
    const int lane = t & 31, wid = t >> 5;       // 8 warps
    const int g = lane >> 2, tg = lane & 3;
    const int mt = blockIdx.x >> 1;
    const int nh = blockIdx.x & 1;
    const bool is_sq = mt < NSQT;
    const float* Asrc = is_sq ? (g_h2sq + (size_t)mt * 16384)
                              : (g_h2pc + (size_t)(mt - NSQT) * 16384);

    // stage B hi/lo: 8192 u32 per tile, 32 per thread
    {
        const uint32_t* sH = (const uint32_t*)(g_Bt + (nh * 2 + 0) * 16384);
        const uint32_t* sL = (const uint32_t*)(g_Bt + (nh * 2 + 1) * 16384);
        #pragma unroll
        for (int i = 0; i < 32; i++) {
            int e = t + i * 256;
            int n = e >> 6, kp = (e & 63) * 2;
            ((uint32_t*)Bhi)[(n * PADK + kp) >> 1] = sH[e];
            ((uint32_t*)Blo)[(n * PADK + kp) >> 1] = sL[e];
        }
    }
    // stage A: fp32 -> bf16 hi/lo, padded plain layout
    {
        #pragma unroll
        for (int i = 0; i < 16; i++) {
            int e = t + i * 256;            // float4 granule 0..4095
            int r = e >> 5, k0 = (e & 31) * 4;
            float4 v = *(const float4*)&Asrc[r * 128 + k0];
            __nv_bfloat162 h0 = __floats2bfloat162_rn(v.x, v.y);
            __nv_bfloat162 h1 = __floats2bfloat162_rn(v.z, v.w);
            float lx = v.x - __bfloat162float(h0.x), ly = v.y - __bfloat162float(h0.y);
            float lz = v.z - __bfloat162float(h1.x), lw = v.w - __bfloat162float(h1.y);
            __nv_bfloat162 l0 = __floats2bfloat162_rn(lx, ly);
            __nv_bfloat162 l1 = __floats2bfloat162_rn(lz, lw);
            int o = r * PADK + k0;
            *(uint2*)&Ahi[o] = make_uint2(*(uint32_t*)&h0, *(uint32_t*)&h1);
            *(uint2*)&Alo[o] = make_uint2(*(uint32_t*)&l0, *(uint32_t*)&l1);
        }
    }
    __syncthreads();

    float c[16][4];
    #pragma unroll
    for (int j = 0; j < 16; j++)
        #pragma unroll
        for (int q = 0; q < 4; q++) c[j][q] = 0.f;

    const int ra = wid * 16 + g;
    #pragma unroll
    for (int p = 0; p < 3; p++) {
        const __nv_bfloat16* As = (p == 2) ? Alo : Ahi;
        const __nv_bfloat16* Bs = (p == 1) ? Blo : Bhi;
        for (int kk = 0; kk < 8; kk++) {
            const int kb = kk * 16 + tg * 2;
            uint32_t a0 = *(const uint32_t*)&As[ra * PADK + kb];
            uint32_t a1 = *(const uint32_t*)&As[(ra + 8) * PADK + kb];
            uint32_t a2 = *(const uint32_t*)&As[ra * PADK + kb + 8];
            uint32_t a3 = *(const uint32_t*)&As[(ra + 8) * PADK + kb + 8];
            #pragma unroll
            for (int j = 0; j < 16; j++) {
                const int nb = j * 8 + g;
                uint32_t b0 = *(const uint32_t*)&Bs[nb * PADK + kb];
                uint32_t b1 = *(const uint32_t*)&Bs[nb * PADK + kb + 8];
                mma_bf16(c[j], a0, a1, a2, a3, b0, b1);
            }
        }
    }
    __syncthreads();

    // epilogue: bias+gelu into smem scratch (reuses A region), then board-mean
    float* scr = (float*)smraw;     // [128][SCRP]
    #pragma unroll
    for (int j = 0; j < 16; j++) {
        int col = j * 8 + tg * 2;
        float bo0 = b_out[nh * 128 + col];
        float bo1 = b_out[nh * 128 + col + 1];
        scr[(wid * 16 + g) * SCRP + col]         = gelu_f(c[j][0] + bo0);
        scr[(wid * 16 + g) * SCRP + col + 1]     = gelu_f(c[j][1] + bo1);
        scr[(wid * 16 + g + 8) * SCRP + col]     = gelu_f(c[j][2] + bo0);
        scr[(wid * 16 + g + 8) * SCRP + col + 1] = gelu_f(c[j][3] + bo1);
    }
    __syncthreads();

    if (t < 128) {
        const int cc = t;
        const int row_base = (is_sq ? mt : (mt - NSQT)) * 128;
        const float scale = is_sq ? (1.0f / 64.0f) : (1.0f / 24.0f);
        int cur = is_sq ? (row_base >> 6) : (row_base / 24);
        float acc = 0.f;
        for (int rr = 0; rr < 128; rr++) {
            int gr = row_base + rr;
            int nbd = is_sq ? (gr >> 6) : (gr / 24);
            if (nbd != cur) {
                atomicAdd(&g_shared[cur * DDIM + nh * 128 + cc], acc * scale);
                acc = 0.f; cur = nbd;
            }
            acc += scr[rr * SCRP + cc];
        }
        atomicAdd(&g_shared[cur * DDIM + nh * 128 + cc], acc * scale);
    }
}

// ============================================================================
// board kernel (phase 4 removed; writes h2 to global)
// ============================================================================
#define OFF_HSQ   0
#define OFF_HPC   8192
#define OFF_RADJ  11264
#define OFF_AGGO  19456
#define OFF_RATT  27648
#define OFF_RDEF  30720
#define OFF_RREV  33792
#define OFF_POCC  36864
#define OFF_WST   39936
#define OFF_EIDX  56320
#define SMEM1_BYTES (56320*4 + 548*4)

__device__ __forceinline__ void pf_load128(float4* pf, const float* W, int t) {
    const float4* W4 = (const float4*)W;
    #pragma unroll
    for (int i = 0; i < 8; i++) pf[i] = W4[t + i * T512];
}
__device__ __forceinline__ void pf_store(float* wst, const float4* pf, int t) {
    float4* w4 = (float4*)wst;
    #pragma unroll
    for (int i = 0; i < 8; i++) w4[t + i * T512] = pf[i];
}
__device__ __forceinline__ float sel4(float4 v, int kk) {
    return kk == 0 ? v.x : kk == 1 ? v.y : kk == 2 ? v.z : v.w;
}
__device__ __forceinline__ void gemm64(const float* __restrict__ A,
                                       const float* __restrict__ wst,
                                       float C[4][4], int rg, int c4) {
    #pragma unroll 2
    for (int k = 0; k < 128; k += 4) {
        float4 a[4];
        #pragma unroll
        for (int i = 0; i < 4; i++) a[i] = *(const float4*)&A[(rg * 4 + i) * 128 + k];
        #pragma unroll
        for (int kk = 0; kk < 4; kk++) {
            float4 bv = *(const float4*)&wst[(k + kk) * 128 + c4];
            #pragma unroll
            for (int i = 0; i < 4; i++) {
                float av = sel4(a[i], kk);
                C[i][0] += av * bv.x; C[i][1] += av * bv.y;
                C[i][2] += av * bv.z; C[i][3] += av * bv.w;
            }
        }
    }
}
__device__ __forceinline__ void gemm24(const float* __restrict__ A,
                                       const float* __restrict__ wst,
                                       float C[3][2], int rg2, int c2) {
    #pragma unroll 2
    for (int k = 0; k < 128; k += 4) {
        float4 a[3];
        #pragma unroll
        for (int i = 0; i < 3; i++) a[i] = *(const float4*)&A[(rg2 * 3 + i) * 128 + k];
        #pragma unroll
        for (int kk = 0; kk < 4; kk++) {
            float2 bv = *(const float2*)&wst[(k + kk) * 128 + c2];
            #pragma unroll
            for (int i = 0; i < 3; i++) {
                float av = sel4(a[i], kk);
                C[i][0] += av * bv.x; C[i][1] += av * bv.y;
            }
        }
    }
}

__global__ void __launch_bounds__(T512, 1) board_kernel(
    const float* __restrict__ x_sq, const float* __restrict__ x_pc,
    const float* __restrict__ W_in_sq, const float* __restrict__ b_in_sq,
    const float* __restrict__ W_in_pc, const float* __restrict__ b_in_pc,
    const float* __restrict__ W_adj, const float* __restrict__ W_occ,
    const float* __restrict__ W_att, const float* __restrict__ W_def,
    const float* __restrict__ W_rev,
    const int* __restrict__ ei_adj, const int* __restrict__ ei_occ,
    const int* __restrict__ ei_att, const int* __restrict__ ei_def,
    const int* __restrict__ ei_rev)
{
    extern __shared__ float sm[];
    float* h_sq   = sm + OFF_HSQ;
    float* h_pc   = sm + OFF_HPC;
    float* rawAdj = sm + OFF_RADJ;
    float* aggO   = sm + OFF_AGGO;
    float* rawAtt = sm + OFF_RATT;
    float* rawDef = sm + OFF_RDEF;
    float* rawRev = sm + OFF_RREV;
    float* p_occ  = sm + OFF_POCC;
    float* wst    = sm + OFF_WST;
    int*   eidx   = (int*)(sm + OFF_EIDX);

    const int b = blockIdx.x;
    const int t = threadIdx.x;

    float4 pf[8];
    pf_load128(pf, W_adj, t);

    {
        const int ba = b * E_ADJ;
        for (int i = t; i < E_ADJ; i += T512) {
            int s = ei_adj[ba + i] - b * SQN;
            int d = ei_adj[NB * E_ADJ + ba + i] - b * SQN;
            eidx[i] = s | (d << 8);
        }
        const int bt = b * E_ATT;
        for (int i = t; i < E_ATT; i += T512) {
            int s  = ei_att[bt + i] - b * PCN;
            int d  = ei_att[NB * E_ATT + bt + i] - b * PCN;
            eidx[E_ADJ + i] = s | (d << 8);
            int s2 = ei_def[bt + i] - b * PCN;
            int d2 = ei_def[NB * E_DEF + bt + i] - b * PCN;
            eidx[E_ADJ + E_ATT + i] = s2 | (d2 << 8);
        }
        const int bo = b * E_OCC;
        for (int i = t; i < E_REV; i += T512) {
            int s = ei_rev[bo + i] - b * SQN;
            int d = ei_rev[NB * E_REV + bo + i] - b * PCN;
            eidx[500 + i] = s | (d << 8);
            int so = ei_occ[bo + i] - b * PCN;
            int dd = ei_occ[NB * E_OCC + bo + i] - b * SQN;
            eidx[524 + i] = so | (dd << 8);
        }
    }
    {
        float4* r4 = (float4*)rawAdj;
        for (int i = t; i < 6400; i += T512) r4[i] = make_float4(0.f, 0.f, 0.f, 0.f);
    }
    float* xs  = wst;
    float* xp  = wst + 1024;
    float* wi1 = wst + 2048;
    float* wi2 = wst + 4096;
    for (int i = t; i < SQN * FDIM; i += T512) xs[i] = x_sq[b * SQN * FDIM + i];
    for (int i = t; i < PCN * FDIM; i += T512) xp[i] = x_pc[b * PCN * FDIM + i];
    for (int i = t; i < FDIM * HDIM; i += T512) { wi1[i] = W_in_sq[i]; wi2[i] = W_in_pc[i]; }
    __syncthreads();

    {
        const int c = t & 127;
        const int q = t >> 7;
        float wcol[16];
        #pragma unroll
        for (int k = 0; k < 16; k++) wcol[k] = wi1[k * 128 + c];
        float bias = b_in_sq[c];
        for (int r = q * 16; r < q * 16 + 16; r++) {
            float acc = bias;
            #pragma unroll
            for (int k = 0; k < 16; k++) acc += xs[r * 16 + k] * wcol[k];
            h_sq[r * 128 + c] = gelu_f(acc);
        }
        #pragma unroll
        for (int k = 0; k < 16; k++) wcol[k] = wi2[k * 128 + c];
        bias = b_in_pc[c];
        for (int r = q * 6; r < q * 6 + 6; r++) {
            float acc = bias;
            #pragma unroll
            for (int k = 0; k < 16; k++) acc += xp[r * 16 + k] * wcol[k];
            h_pc[r * 128 + c] = gelu_f(acc);
        }
    }
    __syncthreads();

    {
        const int g = t >> 7;
        const int c = t & 127;
        for (int i = g; i < E_ADJ; i += 4) {
            int e = eidx[i];
            atomicAdd(&rawAdj[(e >> 8) * 128 + c], h_sq[(e & 255) * 128 + c]);
        }
        for (int i = g; i < E_ATT; i += 4) {
            int e = eidx[E_ADJ + i];
            atomicAdd(&rawAtt[(e >> 8) * 128 + c], h_pc[(e & 255) * 128 + c]);
        }
        for (int i = g; i < E_DEF; i += 4) {
            int e = eidx[E_ADJ + E_ATT + i];
            atomicAdd(&rawDef[(e >> 8) * 128 + c], h_pc[(e & 255) * 128 + c]);
        }
        for (int i = g; i < E_REV; i += 4) {
            int e = eidx[500 + i];
            atomicAdd(&rawRev[(e >> 8) * 128 + c], h_sq[(e & 255) * 128 + c]);
        }
    }
    __syncthreads();

    const int c4  = (t & 31) * 4;
    const int rg  = t >> 5;
    const int c2  = (t & 63) * 2;
    const int rg2 = t >> 6;

    pf_store(wst, pf, t);
    pf_load128(pf, W_occ, t);
    __syncthreads();

    float Cadj[4][4];
    #pragma unroll
    for (int i = 0; i < 4; i++)
        #pragma unroll
        for (int j = 0; j < 4; j++) Cadj[i][j] = 0.f;
    gemm64(rawAdj, wst, Cadj, rg, c4);
    __syncthreads();

    pf_store(wst, pf, t);
    pf_load128(pf, W_att, t);
    __syncthreads();

    {
        float C[3][2] = {{0.f,0.f},{0.f,0.f},{0.f,0.f}};
        gemm24(h_pc, wst, C, rg2, c2);
        #pragma unroll
        for (int i = 0; i < 3; i++) {
            p_occ[(rg2 * 3 + i) * 128 + c2]     = C[i][0];
            p_occ[(rg2 * 3 + i) * 128 + c2 + 1] = C[i][1];
        }
    }
    __syncthreads();

    pf_store(wst, pf, t);
    pf_load128(pf, W_def, t);
    {
        const int g = t >> 7;
        const int c = t & 127;
        for (int i = g; i < E_OCC; i += 4) {
            int e = eidx[524 + i];
            atomicAdd(&aggO[(e >> 8) * 128 + c], p_occ[(e & 255) * 128 + c]);
        }
    }
    __syncthreads();

    #pragma unroll
    for (int i = 0; i < 4; i++) {
        int r = rg * 4 + i;
        #pragma unroll
        for (int j = 0; j < 4; j++) {
            float v = h_sq[r * 128 + c4 + j] + Cadj[i][j] + aggO[r * 128 + c4 + j];
            h_sq[r * 128 + c4 + j] = gelu_f(v);
        }
    }

    float Cpc[3][2] = {{0.f,0.f},{0.f,0.f},{0.f,0.f}};
    gemm24(rawAtt, wst, Cpc, rg2, c2);
    __syncthreads();
    pf_store(wst, pf, t);
    pf_load128(pf, W_rev, t);
    __syncthreads();
    gemm24(rawDef, wst, Cpc, rg2, c2);
    __syncthreads();
    pf_store(wst, pf, t);
    __syncthreads();
    gemm24(rawRev, wst, Cpc, rg2, c2);
    #pragma unroll
    for (int i = 0; i < 3; i++) {
        int r = rg2 * 3 + i;
        #pragma unroll
        for (int j = 0; j < 2; j++) {
            float v = h_pc[r * 128 + c2 + j] + Cpc[i][j];
            h_pc[r * 128 + c2 + j] = gelu_f(v);
        }
    }
    __syncthreads();

    {
        float4* dq = (float4*)(g_h2sq + (size_t)b * SQN * HDIM);
        const float4* sq4 = (const float4*)h_sq;
        #pragma unroll
        for (int i = 0; i < 4; i++) dq[t + i * T512] = sq4[t + i * T512];
        float4* dp = (float4*)(g_h2pc + (size_t)b * PCN * HDIM);
        const float4* pc4 = (const float4*)h_pc;
        for (int i = t; i < 768; i += T512) dp[i] = pc4[i];
    }
}

// ============================================================================
#define SMEM2_BYTES ((4096 + 32768) * 4)
__global__ void __launch_bounds__(256) heads_kernel(
    const float* __restrict__ W_pt, const float* __restrict__ b_pt,
    const float* __restrict__ W_vt, const float* __restrict__ b_vt)
{
    extern __shared__ float sm[];
    float* At = sm;
    float* Bt = sm + 4096;
    const int t = threadIdx.x;
    const int r0 = blockIdx.x * 16;
    for (int i = t; i < 16 * 256; i += 256) At[i] = g_shared[r0 * 256 + i];
    const int c4 = (t & 31) * 4;
    const int rg = t >> 5;
    #pragma unroll
    for (int w = 0; w < 2; w++) {
        __syncthreads();
        const float* W  = w ? W_vt : W_pt;
        const float* bb = w ? b_vt : b_pt;
        float* outp     = w ? g_vt : g_pt;
        for (int i = t; i < 256 * 128; i += 256) Bt[i] = W[i];
        __syncthreads();
        float C[2][4] = {{0.f, 0.f, 0.f, 0.f}, {0.f, 0.f, 0.f, 0.f}};
        #pragma unroll 2
        for (int k = 0; k < 256; k += 4) {
            float4 a0 = *(const float4*)&At[(rg * 2) * 256 + k];
            float4 a1 = *(const float4*)&At[(rg * 2 + 1) * 256 + k];
            #pragma unroll
            for (int kk = 0; kk < 4; kk++) {
                float4 bv = *(const float4*)&Bt[(k + kk) * 128 + c4];
                float v0 = sel4(a0, kk), v1 = sel4(a1, kk);
                C[0][0] += v0 * bv.x; C[0][1] += v0 * bv.y; C[0][2] += v0 * bv.z; C[0][3] += v0 * bv.w;
                C[1][0] += v1 * bv.x; C[1][1] += v1 * bv.y; C[1][2] += v1 * bv.z; C[1][3] += v1 * bv.w;
            }
        }
        #pragma unroll
        for (int i = 0; i < 2; i++) {
            int r = r0 + rg * 2 + i;
            float4 o;
            o.x = gelu_f(C[i][0] + bb[c4 + 0]);
            o.y = gelu_f(C[i][1] + bb[c4 + 1]);
            o.z = gelu_f(C[i][2] + bb[c4 + 2]);
            o.w = gelu_f(C[i][3] + bb[c4 + 3]);
            *(float4*)&outp[r * 128 + c4] = o;
        }
    }
}

#define SMEM3_BYTES ((8192 + 16384) * 4)
__global__ void __launch_bounds__(256) policy_kernel(
    const float* __restrict__ W_ph, const float* __restrict__ b_ph,
    float* __restrict__ out)
{
    extern __shared__ float sm[];
    float* At = sm;
    float* Bt = sm + 8192;
    const int t = threadIdx.x;
    const int rb = blockIdx.y * 64;
    const int cb = blockIdx.x * 128;
    for (int i = t; i < 64 * 128; i += 256) At[i] = g_pt[rb * 128 + i];
    for (int m = t; m < 128 * 128; m += 256) {
        int k = m >> 7, j = m & 127;
        int col = cb + j;
        Bt[m] = (col < ADIM) ? W_ph[k * ADIM + col] : 0.f;
    }
    __syncthreads();
    const int c4 = (t & 31) * 4;
    const int rg = t >> 5;
    float C[8][4];
    #pragma unroll
    for (int i = 0; i < 8; i++)
        #pragma unroll
        for (int j = 0; j < 4; j++) C[i][j] = 0.f;
    #pragma unroll 2
    for (int k = 0; k < 128; k += 4) {
        float4 a[8];
        #pragma unroll
        for (int i = 0; i < 8; i++) a[i] = *(const float4*)&At[(rg * 8 + i) * 128 + k];
        #pragma unroll
        for (int kk = 0; kk < 4; kk++) {
            float4 bv = *(const float4*)&Bt[(k + kk) * 128 + c4];
            #pragma unroll
            for (int i = 0; i < 8; i++) {
                float av = sel4(a[i], kk);
                C[i][0] += av * bv.x; C[i][1] += av * bv.y;
                C[i][2] += av * bv.z; C[i][3] += av * bv.w;
            }
        }
    }
    #pragma unroll
    for (int i = 0; i < 8; i++) {
        int r = rb + rg * 8 + i;
        #pragma unroll
        for (int j = 0; j < 4; j++) {
            int col = cb + c4 + j;
            if (col < ADIM) out[r * ADIM + col] = C[i][j] + b_ph[col];
        }
    }
}

__global__ void __launch_bounds__(256) value_kernel(
    const float* __restrict__ W_vh, const float* __restrict__ b_vh,
    float* __restrict__ out)
{
    int r = blockIdx.x * 8 + (threadIdx.x >> 5);
    int lane = threadIdx.x & 31;
    float acc = 0.f;
    #pragma unroll
    for (int q = 0; q < 4; q++)
        acc += g_vt[r * 128 + q * 32 + lane] * W_vh[q * 32 + lane];
    #pragma unroll
    for (int o = 16; o; o >>= 1) acc += __shfl_xor_sync(0xffffffffu, acc, o);
    if (lane == 0) out[(size_t)NB * ADIM + r] = tanhf(acc + b_vh[0]);
}

extern "C" void kernel_launch(void* const* d_in, const int* in_sizes, int n_in,
                              void* d_out, int out_size) {
    (void)in_sizes; (void)n_in; (void)out_size;
    const float* x_sq    = (const float*)d_in[0];
    const float* x_pc    = (const float*)d_in[1];
    const float* W_in_sq = (const float*)d_in[2];
    const float* b_in_sq = (const float*)d_in[3];
    const float* W_in_pc = (const float*)d_in[4];
    const float* b_in_pc = (const float*)d_in[5];
    const float* W_adj   = (const float*)d_in[6];
    const float* W_occ   = (const float*)d_in[7];
    const float* W_att   = (const float*)d_in[8];
    const float* W_def   = (const float*)d_in[9];
    const float* W_rev   = (const float*)d_in[10];
    const float* W_out   = (const float*)d_in[11];
    const float* b_out   = (const float*)d_in[12];
    const float* W_pt    = (const float*)d_in[13];
    const float* b_pt    = (const float*)d_in[14];
    const float* W_vt    = (const float*)d_in[15];
    const float* b_vt    = (const float*)d_in[16];
    const float* W_ph    = (const float*)d_in[17];
    const float* b_ph    = (const float*)d_in[18];
    const float* W_vh    = (const float*)d_in[19];
    const float* b_vh    = (const float*)d_in[20];
    const int* ei_adj    = (const int*)d_in[21];
    const int* ei_occ    = (const int*)d_in[22];
    const int* ei_att    = (const int*)d_in[23];
    const int* ei_def    = (const int*)d_in[24];
    const int* ei_rev    = (const int*)d_in[25];
    float* out = (float*)d_out;

    cudaFuncSetAttribute(board_kernel,   cudaFuncAttributeMaxDynamicSharedMemorySize, SMEM1_BYTES);
    cudaFuncSetAttribute(outgemm_kernel, cudaFuncAttributeMaxDynamicSharedMemorySize, OG_SMEM);
    cudaFuncSetAttribute(heads_kernel,   cudaFuncAttributeMaxDynamicSharedMemorySize, SMEM2_BYTES);
    cudaFuncSetAttribute(policy_kernel,  cudaFuncAttributeMaxDynamicSharedMemorySize, SMEM3_BYTES);

    prep_kernel<<<128, 256>>>(W_out);

    board_kernel<<<NB, T512, SMEM1_BYTES>>>(
        x_sq, x_pc, W_in_sq, b_in_sq, W_in_pc, b_in_pc,
        W_adj, W_occ, W_att, W_def, W_rev,
        ei_adj, ei_occ, ei_att, ei_def, ei_rev);

    outgemm_kernel<<<(NSQT + NPCT) * 2, 256, OG_SMEM>>>(b_out);

    heads_kernel<<<NB / 16, 256, SMEM2_BYTES>>>(W_pt, b_pt, W_vt, b_vt);

    policy_kernel<<<dim3((ADIM + 127) / 128, NB / 64), 256, SMEM3_BYTES>>>(W_ph, b_ph, out);

    value_kernel<<<NB / 8, 256>>>(W_vh, b_vh, out);
}

// round 12
// speedup vs baseline: 1.2102x; 1.0539x over previous
#include <cuda_runtime.h>
#include <cuda_bf16.h>
#include <math.h>
#include <stdint.h>

#define NB   2048
#define SQN  64
#define PCN  24
#define FDIM 16
#define HDIM 128
#define DDIM 256
#define TDIM 128
#define ADIM 4672
#define E_ADJ 420
#define E_OCC 24
#define E_ATT 40
#define E_DEF 40
#define E_REV 24
#define T512 512
#define NSQT 1024
#define NPCT 384
#define PCSEC (NPCT * 16384)

__device__ float g_shared[NB * DDIM];
__device__ float g_pt[NB * TDIM];
__device__ float g_vt[NB * TDIM];
__device__ float g_hsq[NB * SQN * HDIM];        // h_sq (residual)
__device__ float g_rawsq[NB * SQN * HDIM];      // rawAdj -> aggsq -> h2sq
__device__ float g_hpc[NB * PCN * HDIM];        // h_pc -> h2pc
__device__ float g_rawpc[3 * NB * PCN * HDIM];  // att|def|rev raws; agg -> sec0
__device__ float g_pocc[NB * PCN * HDIM];
__device__ __nv_bfloat16 g_Wimg[7 * 2 * 16384]; // adj,occ,att,def,rev,out0,out1 [hi|lo][n][k]

__device__ __forceinline__ float gelu_f(float x) {
    float u = 0.7978845608028654f * x + 0.0356774081f * x * x * x;
    float au = fabsf(u);
    float e = __expf(-2.0f * au);
    float t = __fdividef(1.0f - e, 1.0f + e);
    t = copysignf(t, u);
    return 0.5f * x * (1.0f + t);
}
__device__ __forceinline__ float sel4(float4 v, int kk) {
    return kk == 0 ? v.x : kk == 1 ? v.y : kk == 2 ? v.z : v.w;
}
__device__ __forceinline__ void mma_bf16(float c[4], uint32_t a0, uint32_t a1,
                                         uint32_t a2, uint32_t a3,
                                         uint32_t b0, uint32_t b1) {
    asm volatile(
        "mma.sync.aligned.m16n8k16.row.col.f32.bf16.bf16.f32 "
        "{%0,%1,%2,%3}, {%4,%5,%6,%7}, {%8,%9}, {%0,%1,%2,%3};"
        : "+f"(c[0]), "+f"(c[1]), "+f"(c[2]), "+f"(c[3])
        : "r"(a0), "r"(a1), "r"(a2), "r"(a3), "r"(b0), "r"(b1));
}

// ---------------- shared HMMA tile machinery (128x128xK=128, 256 thr) -------
#define PADK 136
#define TILEB (128 * PADK * 2)
#define SM_AHI 0
#define SM_ALO TILEB
#define SM_BHI (2 * TILEB)
#define SM_BLO (3 * TILEB)
#define TILE_SMEM (4 * TILEB)
#define SCRP 132

__device__ __forceinline__ void stage_Bimg(__nv_bfloat16* Bhi, __nv_bfloat16* Blo,
                                           int img, int t) {
    const uint32_t* sH = (const uint32_t*)(g_Wimg + img * 32768);
    const uint32_t* sL = sH + 8192;
    #pragma unroll
    for (int i = 0; i < 32; i++) {
        int e = t + i * 256;
        int n = e >> 6, kp = (e & 63) * 2;
        ((uint32_t*)Bhi)[(n * PADK + kp) >> 1] = sH[e];
        ((uint32_t*)Blo)[(n * PADK + kp) >> 1] = sL[e];
    }
}
__device__ __forceinline__ void stage_Asrc(__nv_bfloat16* Ahi, __nv_bfloat16* Alo,
                                           const float* __restrict__ Asrc, int t) {
    #pragma unroll
    for (int i = 0; i < 16; i++) {
        int e = t + i * 256;
        int r = e >> 5, k0 = (e & 31) * 4;
        float4 v = *(const float4*)&Asrc[r * 128 + k0];
        __nv_bfloat162 h0 = __floats2bfloat162_rn(v.x, v.y);
        __nv_bfloat162 h1 = __floats2bfloat162_rn(v.z, v.w);
        __nv_bfloat162 l0 = __floats2bfloat162_rn(v.x - __bfloat162float(h0.x),
                                                  v.y - __bfloat162float(h0.y));
        __nv_bfloat162 l1 = __floats2bfloat162_rn(v.z - __bfloat162float(h1.x),
                                                  v.w - __bfloat162float(h1.y));
        int o = r * PADK + k0;
        *(uint2*)&Ahi[o] = make_uint2(*(uint32_t*)&h0, *(uint32_t*)&h1);
        *(uint2*)&Alo[o] = make_uint2(*(uint32_t*)&l0, *(uint32_t*)&l1);
    }
}
__device__ __forceinline__ void mma_3pass(float c[16][4],
                                          const __nv_bfloat16* Ahi, const __nv_bfloat16* Alo,
                                          const __nv_bfloat16* Bhi, const __nv_bfloat16* Blo,
                                          int wid, int g, int tg) {
    const int ra = wid * 16 + g;
    #pragma unroll
    for (int p = 0; p < 3; p++) {
        const __nv_bfloat16* As = (p == 2) ? Alo : Ahi;
        const __nv_bfloat16* Bs = (p == 1) ? Blo : Bhi;
        for (int kk = 0; kk < 8; kk++) {
            const int kb = kk * 16 + tg * 2;
            uint32_t a0 = *(const uint32_t*)&As[ra * PADK + kb];
            uint32_t a1 = *(const uint32_t*)&As[(ra + 8) * PADK + kb];
            uint32_t a2 = *(const uint32_t*)&As[ra * PADK + kb + 8];
            uint32_t a3 = *(const uint32_t*)&As[(ra + 8) * PADK + kb + 8];
            #pragma unroll
            for (int j = 0; j < 16; j++) {
                const int nb = j * 8 + g;
                uint32_t b0 = *(const uint32_t*)&Bs[nb * PADK + kb];
                uint32_t b1 = *(const uint32_t*)&Bs[nb * PADK + kb + 8];
                mma_bf16(c[j], a0, a1, a2, a3, b0, b1);
            }
        }
    }
}

// ============================================================================
// prep: build 7 bf16 hi/lo transposed weight images; zero g_shared
// ============================================================================
__global__ void __launch_bounds__(256) prep_kernel(
    const float* __restrict__ W_adj, const float* __restrict__ W_occ,
    const float* __restrict__ W_att, const float* __restrict__ W_def,
    const float* __restrict__ W_rev, const float* __restrict__ W_out)
{
    const float* Ws[5] = {W_adj, W_occ, W_att, W_def, W_rev};
    int tid = blockIdx.x * 256 + threadIdx.x;
    int stride = gridDim.x * 256;
    for (int i = tid; i < NB * DDIM; i += stride) g_shared[i] = 0.f;
    for (int i = tid; i < 7 * 16384; i += stride) {
        int idx = i >> 14, n = (i >> 7) & 127, k = i & 127;
        float v = (idx < 5) ? Ws[idx][k * 128 + n] : W_out[k * 256 + (idx - 5) * 128 + n];
        __nv_bfloat16 hi = __float2bfloat16(v);
        __nv_bfloat16 lo = __float2bfloat16(v - __bfloat162float(hi));
        g_Wimg[idx * 32768 + n * 128 + k] = hi;
        g_Wimg[idx * 32768 + 16384 + n * 128 + k] = lo;
    }
}

// ============================================================================
// stage1: per board — input GEMM + gelu + edge aggregation; write h & raws
// ============================================================================
#define S1_HSQ  0
#define S1_HPC  8192
#define S1_RADJ 11264
#define S1_RATT 19456
#define S1_RDEF 22528
#define S1_RREV 25600
#define S1_XS   28672
#define S1_XP   29696
#define S1_WI1  30080
#define S1_WI2  32128
#define S1_EIDX 34176
#define S1_BYTES ((34176 + 524) * 4)

__global__ void __launch_bounds__(T512, 1) stage1_kernel(
    const float* __restrict__ x_sq, const float* __restrict__ x_pc,
    const float* __restrict__ W_in_sq, const float* __restrict__ b_in_sq,
    const float* __restrict__ W_in_pc, const float* __restrict__ b_in_pc,
    const int* __restrict__ ei_adj, const int* __restrict__ ei_att,
    const int* __restrict__ ei_def, const int* __restrict__ ei_rev)
{
    extern __shared__ float sm[];
    float* h_sq = sm + S1_HSQ;
    float* h_pc = sm + S1_HPC;
    float* rawAdj = sm + S1_RADJ;
    float* rawAtt = sm + S1_RATT;
    float* rawDef = sm + S1_RDEF;
    float* rawRev = sm + S1_RREV;
    int* eidx = (int*)(sm + S1_EIDX);
    const int b = blockIdx.x;
    const int t = threadIdx.x;

    {
        const int ba = b * E_ADJ;
        for (int i = t; i < E_ADJ; i += T512) {
            int s = ei_adj[ba + i] - b * SQN;
            int d = ei_adj[NB * E_ADJ + ba + i] - b * SQN;
            eidx[i] = s | (d << 8);
        }
        const int bt = b * E_ATT;
        for (int i = t; i < E_ATT; i += T512) {
            int s = ei_att[bt + i] - b * PCN;
            int d = ei_att[NB * E_ATT + bt + i] - b * PCN;
            eidx[E_ADJ + i] = s | (d << 8);
            int s2 = ei_def[bt + i] - b * PCN;
            int d2 = ei_def[NB * E_DEF + bt + i] - b * PCN;
            eidx[E_ADJ + E_ATT + i] = s2 | (d2 << 8);
        }
        const int bo = b * E_REV;
        for (int i = t; i < E_REV; i += T512) {
            int s = ei_rev[bo + i] - b * SQN;
            int d = ei_rev[NB * E_REV + bo + i] - b * PCN;
            eidx[500 + i] = s | (d << 8);
        }
    }
    {
        float4* r4 = (float4*)rawAdj;   // adj..rev contiguous: 17408 words
        for (int i = t; i < 4352; i += T512) r4[i] = make_float4(0.f, 0.f, 0.f, 0.f);
    }
    {
        float* xs = sm + S1_XS; float* xp = sm + S1_XP;
        float* wi1 = sm + S1_WI1; float* wi2 = sm + S1_WI2;
        for (int i = t; i < SQN * FDIM; i += T512) xs[i] = x_sq[b * SQN * FDIM + i];
        for (int i = t; i < PCN * FDIM; i += T512) xp[i] = x_pc[b * PCN * FDIM + i];
        for (int i = t; i < FDIM * HDIM; i += T512) { wi1[i] = W_in_sq[i]; wi2[i] = W_in_pc[i]; }
    }
    __syncthreads();
    {
        const float* xs = sm + S1_XS; const float* xp = sm + S1_XP;
        const float* wi1 = sm + S1_WI1; const float* wi2 = sm + S1_WI2;
        const int c = t & 127, q = t >> 7;
        float wcol[16];
        #pragma unroll
        for (int k = 0; k < 16; k++) wcol[k] = wi1[k * 128 + c];
        float bias = b_in_sq[c];
        for (int r = q * 16; r < q * 16 + 16; r++) {
            float acc = bias;
            #pragma unroll
            for (int k = 0; k < 16; k++) acc += xs[r * 16 + k] * wcol[k];
            h_sq[r * 128 + c] = gelu_f(acc);
        }
        #pragma unroll
        for (int k = 0; k < 16; k++) wcol[k] = wi2[k * 128 + c];
        bias = b_in_pc[c];
        for (int r = q * 6; r < q * 6 + 6; r++) {
            float acc = bias;
            #pragma unroll
            for (int k = 0; k < 16; k++) acc += xp[r * 16 + k] * wcol[k];
            h_pc[r * 128 + c] = gelu_f(acc);
        }
    }
    __syncthreads();
    {
        const int g = t >> 7, c = t & 127;
        for (int i = g; i < E_ADJ; i += 4) {
            int e = eidx[i];
            atomicAdd(&rawAdj[(e >> 8) * 128 + c], h_sq[(e & 255) * 128 + c]);
        }
        for (int i = g; i < E_ATT; i += 4) {
            int e = eidx[E_ADJ + i];
            atomicAdd(&rawAtt[(e >> 8) * 128 + c], h_pc[(e & 255) * 128 + c]);
        }
        for (int i = g; i < E_DEF; i += 4) {
            int e = eidx[E_ADJ + E_ATT + i];
            atomicAdd(&rawDef[(e >> 8) * 128 + c], h_pc[(e & 255) * 128 + c]);
        }
        for (int i = g; i < E_REV; i += 4) {
            int e = eidx[500 + i];
            atomicAdd(&rawRev[(e >> 8) * 128 + c], h_sq[(e & 255) * 128 + c]);
        }
    }
    __syncthreads();
    {
        float4* d1 = (float4*)(g_hsq + (size_t)b * 8192);
        float4* d2 = (float4*)(g_rawsq + (size_t)b * 8192);
        const float4* s1 = (const float4*)h_sq;
        const float4* s2 = (const float4*)rawAdj;
        #pragma unroll
        for (int i = 0; i < 4; i++) { d1[t + i * T512] = s1[t + i * T512]; d2[t + i * T512] = s2[t + i * T512]; }
        float4* dh = (float4*)(g_hpc + (size_t)b * 3072);
        const float4* sh = (const float4*)h_pc;
        float4* da = (float4*)(g_rawpc + (size_t)b * 3072);
        float4* dd = (float4*)(g_rawpc + (size_t)PCSEC + (size_t)b * 3072);
        float4* dr = (float4*)(g_rawpc + (size_t)2 * PCSEC + (size_t)b * 3072);
        const float4* sa = (const float4*)rawAtt;
        const float4* sd = (const float4*)rawDef;
        const float4* sr = (const float4*)rawRev;
        for (int i = t; i < 768; i += T512) { dh[i] = sh[i]; da[i] = sa[i]; dd[i] = sd[i]; dr[i] = sr[i]; }
    }
}

// ============================================================================
// gemmA: batched HMMA — aggsq / p_occ / aggpc
// ============================================================================
__global__ void __launch_bounds__(256, 1) gemmA_kernel() {
    extern __shared__ uint8_t smraw[];
    __nv_bfloat16* Ahi = (__nv_bfloat16*)(smraw + SM_AHI);
    __nv_bfloat16* Alo = (__nv_bfloat16*)(smraw + SM_ALO);
    __nv_bfloat16* Bhi = (__nv_bfloat16*)(smraw + SM_BHI);
    __nv_bfloat16* Blo = (__nv_bfloat16*)(smraw + SM_BLO);
    const int t = threadIdx.x;
    const int lane = t & 31, wid = t >> 5;
    const int g = lane >> 2, tg = lane & 3;
    const int bx = blockIdx.x;

    float c[16][4];
    #pragma unroll
    for (int j = 0; j < 16; j++)
        #pragma unroll
        for (int q = 0; q < 4; q++) c[j][q] = 0.f;

    float* out;
    if (bx < NSQT) {
        const float* Asrc = g_rawsq + (size_t)bx * 16384;
        stage_Bimg(Bhi, Blo, 0, t);
        stage_Asrc(Ahi, Alo, Asrc, t);
        __syncthreads();
        mma_3pass(c, Ahi, Alo, Bhi, Blo, wid, g, tg);
        out = (float*)Asrc;
    } else if (bx < NSQT + NPCT) {
        const int mt = bx - NSQT;
        stage_Bimg(Bhi, Blo, 1, t);
        stage_Asrc(Ahi, Alo, g_hpc + (size_t)mt * 16384, t);
        __syncthreads();
        mma_3pass(c, Ahi, Alo, Bhi, Blo, wid, g, tg);
        out = g_pocc + (size_t)mt * 16384;
    } else {
        const int mt = bx - NSQT - NPCT;
        #pragma unroll
        for (int s = 0; s < 3; s++) {
            __syncthreads();
            stage_Bimg(Bhi, Blo, 2 + s, t);
            stage_Asrc(Ahi, Alo, g_rawpc + (size_t)s * PCSEC + (size_t)mt * 16384, t);
            __syncthreads();
            mma_3pass(c, Ahi, Alo, Bhi, Blo, wid, g, tg);
        }
        out = g_rawpc + (size_t)mt * 16384;
    }
    __syncthreads();
    #pragma unroll
    for (int j = 0; j < 16; j++) {
        int col = j * 8 + tg * 2;
        int r0 = wid * 16 + g;
        *(float2*)&out[r0 * 128 + col] = make_float2(c[j][0], c[j][1]);
        *(float2*)&out[(r0 + 8) * 128 + col] = make_float2(c[j][2], c[j][3]);
    }
}

// ============================================================================
// stage2: residual + occ scatter + gelu -> h2 (in place)
// ============================================================================
__global__ void __launch_bounds__(128) stage2_kernel(const int* __restrict__ ei_occ) {
    __shared__ float agg[SQN * HDIM];
    const int b = blockIdx.x;
    const int c = threadIdx.x;
    for (int r = 0; r < SQN; r++) agg[r * 128 + c] = g_rawsq[(size_t)b * 8192 + r * 128 + c];
    for (int i = 0; i < E_OCC; i++) {
        int sp = ei_occ[b * E_OCC + i] - b * PCN;
        int d  = ei_occ[NB * E_OCC + b * E_OCC + i] - b * SQN;
        agg[d * 128 + c] += g_pocc[((size_t)b * PCN + sp) * 128 + c];
    }
    for (int r = 0; r < SQN; r++) {
        size_t o = (size_t)b * 8192 + r * 128 + c;
        g_rawsq[o] = gelu_f(g_hsq[o] + agg[r * 128 + c]);
    }
    for (int r = 0; r < PCN; r++) {
        size_t o = (size_t)b * 3072 + r * 128 + c;
        g_hpc[o] = gelu_f(g_hpc[o] + g_rawpc[o]);
    }
}

// ============================================================================
// outgemm: D = h2 @ W_out; epilogue bias+gelu+board-mean (HMMA, as R11)
// ============================================================================
__global__ void __launch_bounds__(256, 1) outgemm_kernel(const float* __restrict__ b_out) {
    extern __shared__ uint8_t smraw[];
    __nv_bfloat16* Ahi = (__nv_bfloat16*)(smraw + SM_AHI);
    __nv_bfloat16* Alo = (__nv_bfloat16*)(smraw + SM_ALO);
    __nv_bfloat16* Bhi = (__nv_bfloat16*)(smraw + SM_BHI);
    __nv_bfloat16* Blo = (__nv_bfloat16*)(smraw + SM_BLO);
    const int t = threadIdx.x;
    const int lane = t & 31, wid = t >> 5;
    const int g = lane >> 2, tg = lane & 3;
    const int mt = blockIdx.x >> 1;
    const int nh = blockIdx.x & 1;
    const bool is_sq = mt < NSQT;
    const float* Asrc = is_sq ? (g_rawsq + (size_t)mt * 16384)
                              : (g_hpc + (size_t)(mt - NSQT) * 16384);

    stage_Bimg(Bhi, Blo, 5 + nh, t);
    stage_Asrc(Ahi, Alo, Asrc, t);
    __syncthreads();

    float c[16][4];
    #pragma unroll
    for (int j = 0; j < 16; j++)
        #pragma unroll
        for (int q = 0; q < 4; q++) c[j][q] = 0.f;
    mma_3pass(c, Ahi, Alo, Bhi, Blo, wid, g, tg);
    __syncthreads();

    float* scr = (float*)smraw;
    #pragma unroll
    for (int j = 0; j < 16; j++) {
        int col = j * 8 + tg * 2;
        float bo0 = b_out[nh * 128 + col];
        float bo1 = b_out[nh * 128 + col + 1];
        scr[(wid * 16 + g) * SCRP + col]         = gelu_f(c[j][0] + bo0);
        scr[(wid * 16 + g) * SCRP + col + 1]     = gelu_f(c[j][1] + bo1);
        scr[(wid * 16 + g + 8) * SCRP + col]     = gelu_f(c[j][2] + bo0);
        scr[(wid * 16 + g + 8) * SCRP + col + 1] = gelu_f(c[j][3] + bo1);
    }
    __syncthreads();
    if (t < 128) {
        const int cc = t;
        const int row_base = (is_sq ? mt : (mt - NSQT)) * 128;
        const float scale = is_sq ? (1.0f / 64.0f) : (1.0f / 24.0f);
        int cur = is_sq ? (row_base >> 6) : (row_base / 24);
        float acc = 0.f;
        for (int rr = 0; rr < 128; rr++) {
            int gr = row_base + rr;
            int nbd = is_sq ? (gr >> 6) : (gr / 24);
            if (nbd != cur) {
                atomicAdd(&g_shared[cur * DDIM + nh * 128 + cc], acc * scale);
                acc = 0.f; cur = nbd;
            }
            acc += scr[rr * SCRP + cc];
        }
        atomicAdd(&g_shared[cur * DDIM + nh * 128 + cc], acc * scale);
    }
}

// ============================================================================
#define SMEM2_BYTES ((4096 + 32768) * 4)
__global__ void __launch_bounds__(256) heads_kernel(
    const float* __restrict__ W_pt, const float* __restrict__ b_pt,
    const float* __restrict__ W_vt, const float* __restrict__ b_vt)
{
    extern __shared__ float sm[];
    float* At = sm;
    float* Bt = sm + 4096;
    const int t = threadIdx.x;
    const int r0 = blockIdx.x * 16;
    for (int i = t; i < 16 * 256; i += 256) At[i] = g_shared[r0 * 256 + i];
    const int c4 = (t & 31) * 4;
    const int rg = t >> 5;
    #pragma unroll
    for (int w = 0; w < 2; w++) {
        __syncthreads();
        const float* W  = w ? W_vt : W_pt;
        const float* bb = w ? b_vt : b_pt;
        float* outp     = w ? g_vt : g_pt;
        for (int i = t; i < 256 * 128; i += 256) Bt[i] = W[i];
        __syncthreads();
        float C[2][4] = {{0.f, 0.f, 0.f, 0.f}, {0.f, 0.f, 0.f, 0.f}};
        #pragma unroll 2
        for (int k = 0; k < 256; k += 4) {
            float4 a0 = *(const float4*)&At[(rg * 2) * 256 + k];
            float4 a1 = *(const float4*)&At[(rg * 2 + 1) * 256 + k];
            #pragma unroll
            for (int kk = 0; kk < 4; kk++) {
                float4 bv = *(const float4*)&Bt[(k + kk) * 128 + c4];
                float v0 = sel4(a0, kk), v1 = sel4(a1, kk);
                C[0][0] += v0 * bv.x; C[0][1] += v0 * bv.y; C[0][2] += v0 * bv.z; C[0][3] += v0 * bv.w;
                C[1][0] += v1 * bv.x; C[1][1] += v1 * bv.y; C[1][2] += v1 * bv.z; C[1][3] += v1 * bv.w;
            }
        }
        #pragma unroll
        for (int i = 0; i < 2; i++) {
            int r = r0 + rg * 2 + i;
            float4 o;
            o.x = gelu_f(C[i][0] + bb[c4 + 0]);
            o.y = gelu_f(C[i][1] + bb[c4 + 1]);
            o.z = gelu_f(C[i][2] + bb[c4 + 2]);
            o.w = gelu_f(C[i][3] + bb[c4 + 3]);
            *(float4*)&outp[r * 128 + c4] = o;
        }
    }
}

#define SMEM3_BYTES ((8192 + 16384) * 4)
__global__ void __launch_bounds__(256) policy_kernel(
    const float* __restrict__ W_ph, const float* __restrict__ b_ph,
    float* __restrict__ out)
{
    extern __shared__ float sm[];
    float* At = sm;
    float* Bt = sm + 8192;
    const int t = threadIdx.x;
    const int rb = blockIdx.y * 64;
    const int cb = blockIdx.x * 128;
    for (int i = t; i < 64 * 128; i += 256) At[i] = g_pt[rb * 128 + i];
    for (int m = t; m < 128 * 128; m += 256) {
        int k = m >> 7, j = m & 127;
        int col = cb + j;
        Bt[m] = (col < ADIM) ? W_ph[k * ADIM + col] : 0.f;
    }
    __syncthreads();
    const int c4 = (t & 31) * 4;
    const int rg = t >> 5;
    float C[8][4];
    #pragma unroll
    for (int i = 0; i < 8; i++)
        #pragma unroll
        for (int j = 0; j < 4; j++) C[i][j] = 0.f;
    #pragma unroll 2
    for (int k = 0; k < 128; k += 4) {
        float4 a[8];
        #pragma unroll
        for (int i = 0; i < 8; i++) a[i] = *(const float4*)&At[(rg * 8 + i) * 128 + k];
        #pragma unroll
        for (int kk = 0; kk < 4; kk++) {
            float4 bv = *(const float4*)&Bt[(k + kk) * 128 + c4];
            #pragma unroll
            for (int i = 0; i < 8; i++) {
                float av = sel4(a[i], kk);
                C[i][0] += av * bv.x; C[i][1] += av * bv.y;
                C[i][2] += av * bv.z; C[i][3] += av * bv.w;
            }
        }
    }
    #pragma unroll
    for (int i = 0; i < 8; i++) {
        int r = rb + rg * 8 + i;
        #pragma unroll
        for (int j = 0; j < 4; j++) {
            int col = cb + c4 + j;
            if (col < ADIM) out[r * ADIM + col] = C[i][j] + b_ph[col];
        }
    }
}

__global__ void __launch_bounds__(256) value_kernel(
    const float* __restrict__ W_vh, const float* __restrict__ b_vh,
    float* __restrict__ out)
{
    int r = blockIdx.x * 8 + (threadIdx.x >> 5);
    int lane = threadIdx.x & 31;
    float acc = 0.f;
    #pragma unroll
    for (int q = 0; q < 4; q++)
        acc += g_vt[r * 128 + q * 32 + lane] * W_vh[q * 32 + lane];
    #pragma unroll
    for (int o = 16; o; o >>= 1) acc += __shfl_xor_sync(0xffffffffu, acc, o);
    if (lane == 0) out[(size_t)NB * ADIM + r] = tanhf(acc + b_vh[0]);
}

extern "C" void kernel_launch(void* const* d_in, const int* in_sizes, int n_in,
                              void* d_out, int out_size) {
    (void)in_sizes; (void)n_in; (void)out_size;
    const float* x_sq    = (const float*)d_in[0];
    const float* x_pc    = (const float*)d_in[1];
    const float* W_in_sq = (const float*)d_in[2];
    const float* b_in_sq = (const float*)d_in[3];
    const float* W_in_pc = (const float*)d_in[4];
    const float* b_in_pc = (const float*)d_in[5];
    const float* W_adj   = (const float*)d_in[6];
    const float* W_occ   = (const float*)d_in[7];
    const float* W_att   = (const float*)d_in[8];
    const float* W_def   = (const float*)d_in[9];
    const float* W_rev   = (const float*)d_in[10];
    const float* W_out   = (const float*)d_in[11];
    const float* b_out   = (const float*)d_in[12];
    const float* W_pt    = (const float*)d_in[13];
    const float* b_pt    = (const float*)d_in[14];
    const float* W_vt    = (const float*)d_in[15];
    const float* b_vt    = (const float*)d_in[16];
    const float* W_ph    = (const float*)d_in[17];
    const float* b_ph    = (const float*)d_in[18];
    const float* W_vh    = (const float*)d_in[19];
    const float* b_vh    = (const float*)d_in[20];
    const int* ei_adj    = (const int*)d_in[21];
    const int* ei_occ    = (const int*)d_in[22];
    const int* ei_att    = (const int*)d_in[23];
    const int* ei_def    = (const int*)d_in[24];
    const int* ei_rev    = (const int*)d_in[25];
    float* out = (float*)d_out;

    cudaFuncSetAttribute(stage1_kernel,  cudaFuncAttributeMaxDynamicSharedMemorySize, S1_BYTES);
    cudaFuncSetAttribute(gemmA_kernel,   cudaFuncAttributeMaxDynamicSharedMemorySize, TILE_SMEM);
    cudaFuncSetAttribute(outgemm_kernel, cudaFuncAttributeMaxDynamicSharedMemorySize, TILE_SMEM);
    cudaFuncSetAttribute(heads_kernel,   cudaFuncAttributeMaxDynamicSharedMemorySize, SMEM2_BYTES);
    cudaFuncSetAttribute(policy_kernel,  cudaFuncAttributeMaxDynamicSharedMemorySize, SMEM3_BYTES);

    prep_kernel<<<128, 256>>>(W_adj, W_occ, W_att, W_def, W_rev, W_out);

    stage1_kernel<<<NB, T512, S1_BYTES>>>(
        x_sq, x_pc, W_in_sq, b_in_sq, W_in_pc, b_in_pc,
        ei_adj, ei_att, ei_def, ei_rev);

    gemmA_kernel<<<NSQT + NPCT + NPCT, 256, TILE_SMEM>>>();

    stage2_kernel<<<NB, 128>>>(ei_occ);

    outgemm_kernel<<<(NSQT + NPCT) * 2, 256, TILE_SMEM>>>(b_out);

    heads_kernel<<<NB / 16, 256, SMEM2_BYTES>>>(W_pt, b_pt, W_vt, b_vt);

    policy_kernel<<<dim3((ADIM + 127) / 128, NB / 64), 256, SMEM3_BYTES>>>(W_ph, b_ph, out);

    value_kernel<<<NB / 8, 256>>>(W_vh, b_vh, out);
}

// round 13
// speedup vs baseline: 1.4505x; 1.1986x over previous
#include <cuda_runtime.h>
#include <cuda_bf16.h>
#include <math.h>
#include <stdint.h>

#define NB   2048
#define SQN  64
#define PCN  24
#define FDIM 16
#define HDIM 128
#define DDIM 256
#define TDIM 128
#define ADIM 4672
#define APAD 4736
#define E_ADJ 420
#define E_OCC 24
#define E_ATT 40
#define E_DEF 40
#define E_REV 24
#define T512 512
#define NSQT 1024
#define NPCT 384
#define PCSEC (NPCT * 16384)

__device__ float g_shared[NB * DDIM];
__device__ float g_pt[NB * TDIM];
__device__ float g_vt[NB * TDIM];
__device__ float g_hsq[NB * SQN * HDIM];
__device__ float g_rawsq[NB * SQN * HDIM];       // rawAdj -> aggsq -> h2sq
__device__ float g_hpc[NB * PCN * HDIM];         // h_pc (read-only after stage1)
__device__ float g_rawpc[3 * NB * PCN * HDIM];   // att|def|rev raws; sec0 -> h2pc
__device__ float g_pocc[NB * PCN * HDIM];
__device__ __nv_bfloat16 g_Wimg[7 * 2 * 16384];  // adj,occ,att,def,rev,out0,out1
__device__ __nv_bfloat16 g_Wph[2 * APAD * 128];  // policy weights, [hi|lo][n][k]

__device__ __forceinline__ float gelu_f(float x) {
    float u = 0.7978845608028654f * x + 0.0356774081f * x * x * x;
    float au = fabsf(u);
    float e = __expf(-2.0f * au);
    float t = __fdividef(1.0f - e, 1.0f + e);
    t = copysignf(t, u);
    return 0.5f * x * (1.0f + t);
}
__device__ __forceinline__ float sel4(float4 v, int kk) {
    return kk == 0 ? v.x : kk == 1 ? v.y : kk == 2 ? v.z : v.w;
}
__device__ __forceinline__ void mma_bf16(float c[4], uint32_t a0, uint32_t a1,
                                         uint32_t a2, uint32_t a3,
                                         uint32_t b0, uint32_t b1) {
    asm volatile(
        "mma.sync.aligned.m16n8k16.row.col.f32.bf16.bf16.f32 "
        "{%0,%1,%2,%3}, {%4,%5,%6,%7}, {%8,%9}, {%0,%1,%2,%3};"
        : "+f"(c[0]), "+f"(c[1]), "+f"(c[2]), "+f"(c[3])
        : "r"(a0), "r"(a1), "r"(a2), "r"(a3), "r"(b0), "r"(b1));
}

// ---------------- shared HMMA tile machinery (128x128xK=128, 256 thr) -------
#define PADK 136
#define TILEB (128 * PADK * 2)
#define TILE_SMEM (4 * TILEB)
#define SCRP 132

__device__ __forceinline__ void stage_Bptr(__nv_bfloat16* Bhi, __nv_bfloat16* Blo,
                                           const uint32_t* sH, const uint32_t* sL, int t) {
    #pragma unroll
    for (int i = 0; i < 32; i++) {
        int e = t + i * 256;
        int n = e >> 6, kp = (e & 63) * 2;
        ((uint32_t*)Bhi)[(n * PADK + kp) >> 1] = sH[e];
        ((uint32_t*)Blo)[(n * PADK + kp) >> 1] = sL[e];
    }
}
__device__ __forceinline__ void stage_Bimg(__nv_bfloat16* Bhi, __nv_bfloat16* Blo,
                                           int img, int t) {
    const uint32_t* sH = (const uint32_t*)(g_Wimg + img * 32768);
    stage_Bptr(Bhi, Blo, sH, sH + 8192, t);
}
__device__ __forceinline__ void stage_Asrc(__nv_bfloat16* Ahi, __nv_bfloat16* Alo,
                                           const float* __restrict__ Asrc, int t) {
    #pragma unroll
    for (int i = 0; i < 16; i++) {
        int e = t + i * 256;
        int r = e >> 5, k0 = (e & 31) * 4;
        float4 v = *(const float4*)&Asrc[r * 128 + k0];
        __nv_bfloat162 h0 = __floats2bfloat162_rn(v.x, v.y);
        __nv_bfloat162 h1 = __floats2bfloat162_rn(v.z, v.w);
        __nv_bfloat162 l0 = __floats2bfloat162_rn(v.x - __bfloat162float(h0.x),
                                                  v.y - __bfloat162float(h0.y));
        __nv_bfloat162 l1 = __floats2bfloat162_rn(v.z - __bfloat162float(h1.x),
                                                  v.w - __bfloat162float(h1.y));
        int o = r * PADK + k0;
        *(uint2*)&Ahi[o] = make_uint2(*(uint32_t*)&h0, *(uint32_t*)&h1);
        *(uint2*)&Alo[o] = make_uint2(*(uint32_t*)&l0, *(uint32_t*)&l1);
    }
}
__device__ __forceinline__ void mma_3pass(float c[16][4],
                                          const __nv_bfloat16* Ahi, const __nv_bfloat16* Alo,
                                          const __nv_bfloat16* Bhi, const __nv_bfloat16* Blo,
                                          int wid, int g, int tg) {
    const int ra = wid * 16 + g;
    #pragma unroll
    for (int p = 0; p < 3; p++) {
        const __nv_bfloat16* As = (p == 2) ? Alo : Ahi;
        const __nv_bfloat16* Bs = (p == 1) ? Blo : Bhi;
        for (int kk = 0; kk < 8; kk++) {
            const int kb = kk * 16 + tg * 2;
            uint32_t a0 = *(const uint32_t*)&As[ra * PADK + kb];
            uint32_t a1 = *(const uint32_t*)&As[(ra + 8) * PADK + kb];
            uint32_t a2 = *(const uint32_t*)&As[ra * PADK + kb + 8];
            uint32_t a3 = *(const uint32_t*)&As[(ra + 8) * PADK + kb + 8];
            #pragma unroll
            for (int j = 0; j < 16; j++) {
                const int nb = j * 8 + g;
                uint32_t b0 = *(const uint32_t*)&Bs[nb * PADK + kb];
                uint32_t b1 = *(const uint32_t*)&Bs[nb * PADK + kb + 8];
                mma_bf16(c[j], a0, a1, a2, a3, b0, b1);
            }
        }
    }
}

// ============================================================================
// prep: 7 GNN weight images + policy weight image; zero g_shared
// ============================================================================
__global__ void __launch_bounds__(256) prep_kernel(
    const float* __restrict__ W_adj, const float* __restrict__ W_occ,
    const float* __restrict__ W_att, const float* __restrict__ W_def,
    const float* __restrict__ W_rev, const float* __restrict__ W_out,
    const float* __restrict__ W_ph)
{
    const float* Ws[5] = {W_adj, W_occ, W_att, W_def, W_rev};
    int tid = blockIdx.x * 256 + threadIdx.x;
    int stride = gridDim.x * 256;
    for (int i = tid; i < NB * DDIM; i += stride) g_shared[i] = 0.f;
    for (int i = tid; i < 7 * 16384; i += stride) {
        int idx = i >> 14, n = (i >> 7) & 127, k = i & 127;
        float v = (idx < 5) ? Ws[idx][k * 128 + n] : W_out[k * 256 + (idx - 5) * 128 + n];
        __nv_bfloat16 hi = __float2bfloat16(v);
        __nv_bfloat16 lo = __float2bfloat16(v - __bfloat162float(hi));
        g_Wimg[idx * 32768 + n * 128 + k] = hi;
        g_Wimg[idx * 32768 + 16384 + n * 128 + k] = lo;
    }
    for (int i = tid; i < APAD * 128; i += stride) {
        int n = i >> 7, k = i & 127;
        float v = (n < ADIM) ? W_ph[k * ADIM + n] : 0.f;
        __nv_bfloat16 hi = __float2bfloat16(v);
        __nv_bfloat16 lo = __float2bfloat16(v - __bfloat162float(hi));
        g_Wph[n * 128 + k] = hi;
        g_Wph[APAD * 128 + n * 128 + k] = lo;
    }
}

// ============================================================================
// stage1: per board — input GEMM + gelu + edge aggregation
// ============================================================================
#define S1_HSQ  0
#define S1_HPC  8192
#define S1_RADJ 11264
#define S1_RATT 19456
#define S1_RDEF 22528
#define S1_RREV 25600
#define S1_XS   28672
#define S1_XP   29696
#define S1_WI1  30080
#define S1_WI2  32128
#define S1_EIDX 34176
#define S1_BYTES ((34176 + 524) * 4)

__global__ void __launch_bounds__(T512, 1) stage1_kernel(
    const float* __restrict__ x_sq, const float* __restrict__ x_pc,
    const float* __restrict__ W_in_sq, const float* __restrict__ b_in_sq,
    const float* __restrict__ W_in_pc, const float* __restrict__ b_in_pc,
    const int* __restrict__ ei_adj, const int* __restrict__ ei_att,
    const int* __restrict__ ei_def, const int* __restrict__ ei_rev)
{
    extern __shared__ float sm[];
    float* h_sq = sm + S1_HSQ;
    float* h_pc = sm + S1_HPC;
    float* rawAdj = sm + S1_RADJ;
    float* rawAtt = sm + S1_RATT;
    float* rawDef = sm + S1_RDEF;
    float* rawRev = sm + S1_RREV;
    int* eidx = (int*)(sm + S1_EIDX);
    const int b = blockIdx.x;
    const int t = threadIdx.x;

    {
        const int ba = b * E_ADJ;
        for (int i = t; i < E_ADJ; i += T512) {
            int s = ei_adj[ba + i] - b * SQN;
            int d = ei_adj[NB * E_ADJ + ba + i] - b * SQN;
            eidx[i] = s | (d << 8);
        }
        const int bt = b * E_ATT;
        for (int i = t; i < E_ATT; i += T512) {
            int s = ei_att[bt + i] - b * PCN;
            int d = ei_att[NB * E_ATT + bt + i] - b * PCN;
            eidx[E_ADJ + i] = s | (d << 8);
            int s2 = ei_def[bt + i] - b * PCN;
            int d2 = ei_def[NB * E_DEF + bt + i] - b * PCN;
            eidx[E_ADJ + E_ATT + i] = s2 | (d2 << 8);
        }
        const int bo = b * E_REV;
        for (int i = t; i < E_REV; i += T512) {
            int s = ei_rev[bo + i] - b * SQN;
            int d = ei_rev[NB * E_REV + bo + i] - b * PCN;
            eidx[500 + i] = s | (d << 8);
        }
    }
    {
        float4* r4 = (float4*)rawAdj;
        for (int i = t; i < 4352; i += T512) r4[i] = make_float4(0.f, 0.f, 0.f, 0.f);
    }
    {
        float* xs = sm + S1_XS; float* xp = sm + S1_XP;
        float* wi1 = sm + S1_WI1; float* wi2 = sm + S1_WI2;
        for (int i = t; i < SQN * FDIM; i += T512) xs[i] = x_sq[b * SQN * FDIM + i];
        for (int i = t; i < PCN * FDIM; i += T512) xp[i] = x_pc[b * PCN * FDIM + i];
        for (int i = t; i < FDIM * HDIM; i += T512) { wi1[i] = W_in_sq[i]; wi2[i] = W_in_pc[i]; }
    }
    __syncthreads();
    {
        const float* xs = sm + S1_XS; const float* xp = sm + S1_XP;
        const float* wi1 = sm + S1_WI1; const float* wi2 = sm + S1_WI2;
        const int c = t & 127, q = t >> 7;
        float wcol[16];
        #pragma unroll
        for (int k = 0; k < 16; k++) wcol[k] = wi1[k * 128 + c];
        float bias = b_in_sq[c];
        for (int r = q * 16; r < q * 16 + 16; r++) {
            float acc = bias;
            #pragma unroll
            for (int k = 0; k < 16; k++) acc += xs[r * 16 + k] * wcol[k];
            h_sq[r * 128 + c] = gelu_f(acc);
        }
        #pragma unroll
        for (int k = 0; k < 16; k++) wcol[k] = wi2[k * 128 + c];
        bias = b_in_pc[c];
        for (int r = q * 6; r < q * 6 + 6; r++) {
            float acc = bias;
            #pragma unroll
            for (int k = 0; k < 16; k++) acc += xp[r * 16 + k] * wcol[k];
            h_pc[r * 128 + c] = gelu_f(acc);
        }
    }
    __syncthreads();
    {
        const int g = t >> 7, c = t & 127;
        for (int i = g; i < E_ADJ; i += 4) {
            int e = eidx[i];
            atomicAdd(&rawAdj[(e >> 8) * 128 + c], h_sq[(e & 255) * 128 + c]);
        }
        for (int i = g; i < E_ATT; i += 4) {
            int e = eidx[E_ADJ + i];
            atomicAdd(&rawAtt[(e >> 8) * 128 + c], h_pc[(e & 255) * 128 + c]);
        }
        for (int i = g; i < E_DEF; i += 4) {
            int e = eidx[E_ADJ + E_ATT + i];
            atomicAdd(&rawDef[(e >> 8) * 128 + c], h_pc[(e & 255) * 128 + c]);
        }
        for (int i = g; i < E_REV; i += 4) {
            int e = eidx[500 + i];
            atomicAdd(&rawRev[(e >> 8) * 128 + c], h_sq[(e & 255) * 128 + c]);
        }
    }
    __syncthreads();
    {
        float4* d1 = (float4*)(g_hsq + (size_t)b * 8192);
        float4* d2 = (float4*)(g_rawsq + (size_t)b * 8192);
        const float4* s1 = (const float4*)h_sq;
        const float4* s2 = (const float4*)rawAdj;
        #pragma unroll
        for (int i = 0; i < 4; i++) { d1[t + i * T512] = s1[t + i * T512]; d2[t + i * T512] = s2[t + i * T512]; }
        float4* dh = (float4*)(g_hpc + (size_t)b * 3072);
        const float4* sh = (const float4*)h_pc;
        float4* da = (float4*)(g_rawpc + (size_t)b * 3072);
        float4* dd = (float4*)(g_rawpc + (size_t)PCSEC + (size_t)b * 3072);
        float4* dr = (float4*)(g_rawpc + (size_t)2 * PCSEC + (size_t)b * 3072);
        const float4* sa = (const float4*)rawAtt;
        const float4* sd = (const float4*)rawDef;
        const float4* sr = (const float4*)rawRev;
        for (int i = t; i < 768; i += T512) { dh[i] = sh[i]; da[i] = sa[i]; dd[i] = sd[i]; dr[i] = sr[i]; }
    }
}

// ============================================================================
// gemmA: heavy pc-agg CTAs first (bx<NPCT, fused residual+gelu epilogue),
// then pocc (NPCT..2*NPCT), then sq-agg (2*NPCT..+NSQT).
// ============================================================================
__global__ void __launch_bounds__(256, 1) gemmA_kernel() {
    extern __shared__ uint8_t smraw[];
    __nv_bfloat16* Ahi = (__nv_bfloat16*)(smraw);
    __nv_bfloat16* Alo = (__nv_bfloat16*)(smraw + TILEB);
    __nv_bfloat16* Bhi = (__nv_bfloat16*)(smraw + 2 * TILEB);
    __nv_bfloat16* Blo = (__nv_bfloat16*)(smraw + 3 * TILEB);
    const int t = threadIdx.x;
    const int lane = t & 31, wid = t >> 5;
    const int g = lane >> 2, tg = lane & 3;
    const int bx = blockIdx.x;

    float c[16][4];
    #pragma unroll
    for (int j = 0; j < 16; j++)
        #pragma unroll
        for (int q = 0; q < 4; q++) c[j][q] = 0.f;

    if (bx < NPCT) {   // pc-agg: 3 accumulated GEMMs + fused h2pc epilogue
        const int mt = bx;
        #pragma unroll
        for (int s = 0; s < 3; s++) {
            __syncthreads();
            stage_Bimg(Bhi, Blo, 2 + s, t);
            stage_Asrc(Ahi, Alo, g_rawpc + (size_t)s * PCSEC + (size_t)mt * 16384, t);
            __syncthreads();
            mma_3pass(c, Ahi, Alo, Bhi, Blo, wid, g, tg);
        }
        float* out = g_rawpc + (size_t)mt * 16384;            // sec0 -> h2pc
        const float* hp = g_hpc + (size_t)mt * 16384;
        __syncthreads();
        #pragma unroll
        for (int j = 0; j < 16; j++) {
            int col = j * 8 + tg * 2;
            int r0 = wid * 16 + g;
            float2 h0 = *(const float2*)&hp[r0 * 128 + col];
            float2 h1 = *(const float2*)&hp[(r0 + 8) * 128 + col];
            *(float2*)&out[r0 * 128 + col] =
                make_float2(gelu_f(h0.x + c[j][0]), gelu_f(h0.y + c[j][1]));
            *(float2*)&out[(r0 + 8) * 128 + col] =
                make_float2(gelu_f(h1.x + c[j][2]), gelu_f(h1.y + c[j][3]));
        }
    } else {
        float* out;
        if (bx < 2 * NPCT) {            // pocc
            const int mt = bx - NPCT;
            stage_Bimg(Bhi, Blo, 1, t);
            stage_Asrc(Ahi, Alo, g_hpc + (size_t)mt * 16384, t);
            out = g_pocc + (size_t)mt * 16384;
        } else {                        // sq-agg
            const int mt = bx - 2 * NPCT;
            stage_Bimg(Bhi, Blo, 0, t);
            stage_Asrc(Ahi, Alo, g_rawsq + (size_t)mt * 16384, t);
            out = g_rawsq + (size_t)mt * 16384;
        }
        __syncthreads();
        mma_3pass(c, Ahi, Alo, Bhi, Blo, wid, g, tg);
        __syncthreads();
        #pragma unroll
        for (int j = 0; j < 16; j++) {
            int col = j * 8 + tg * 2;
            int r0 = wid * 16 + g;
            *(float2*)&out[r0 * 128 + col] = make_float2(c[j][0], c[j][1]);
            *(float2*)&out[(r0 + 8) * 128 + col] = make_float2(c[j][2], c[j][3]);
        }
    }
}

// ============================================================================
// stage2: sq only — agg = rawsq + occ-scatter(pocc); h2sq = gelu(hsq+agg)
// 512 threads, float4 throughout
// ============================================================================
__global__ void __launch_bounds__(T512) stage2_kernel(const int* __restrict__ ei_occ) {
    __shared__ float agg[SQN * HDIM];
    const int b = blockIdx.x;
    const int t = threadIdx.x;
    float4* a4 = (float4*)agg;
    const float4* s4 = (const float4*)(g_rawsq + (size_t)b * 8192);
    #pragma unroll
    for (int i = 0; i < 4; i++) a4[t + i * T512] = s4[t + i * T512];
    __syncthreads();
    {
        const int g = t >> 7, c = t & 127;
        for (int i = g; i < E_OCC; i += 4) {
            int sp = ei_occ[b * E_OCC + i] - b * PCN;
            int d  = ei_occ[NB * E_OCC + b * E_OCC + i] - b * SQN;
            atomicAdd(&agg[d * 128 + c], g_pocc[((size_t)b * PCN + sp) * 128 + c]);
        }
    }
    __syncthreads();
    const float4* h4 = (const float4*)(g_hsq + (size_t)b * 8192);
    float4* o4 = (float4*)(g_rawsq + (size_t)b * 8192);
    #pragma unroll
    for (int i = 0; i < 4; i++) {
        int idx = t + i * T512;
        float4 h = h4[idx];
        float4 a = a4[idx];
        float4 o;
        o.x = gelu_f(h.x + a.x); o.y = gelu_f(h.y + a.y);
        o.z = gelu_f(h.z + a.z); o.w = gelu_f(h.w + a.w);
        o4[idx] = o;
    }
}

// ============================================================================
// outgemm: D = h2 @ W_out; epilogue bias+gelu+board-mean
// ============================================================================
__global__ void __launch_bounds__(256, 1) outgemm_kernel(const float* __restrict__ b_out) {
    extern __shared__ uint8_t smraw[];
    __nv_bfloat16* Ahi = (__nv_bfloat16*)(smraw);
    __nv_bfloat16* Alo = (__nv_bfloat16*)(smraw + TILEB);
    __nv_bfloat16* Bhi = (__nv_bfloat16*)(smraw + 2 * TILEB);
    __nv_bfloat16* Blo = (__nv_bfloat16*)(smraw + 3 * TILEB);
    const int t = threadIdx.x;
    const int lane = t & 31, wid = t >> 5;
    const int g = lane >> 2, tg = lane & 3;
    const int mt = blockIdx.x >> 1;
    const int nh = blockIdx.x & 1;
    const bool is_sq = mt < NSQT;
    const float* Asrc = is_sq ? (g_rawsq + (size_t)mt * 16384)
                              : (g_rawpc + (size_t)(mt - NSQT) * 16384);

    stage_Bimg(Bhi, Blo, 5 + nh, t);
    stage_Asrc(Ahi, Alo, Asrc, t);
    __syncthreads();

    float c[16][4];
    #pragma unroll
    for (int j = 0; j < 16; j++)
        #pragma unroll
        for (int q = 0; q < 4; q++) c[j][q] = 0.f;
    mma_3pass(c, Ahi, Alo, Bhi, Blo, wid, g, tg);
    __syncthreads();

    float* scr = (float*)smraw;
    #pragma unroll
    for (int j = 0; j < 16; j++) {
        int col = j * 8 + tg * 2;
        float bo0 = b_out[nh * 128 + col];
        float bo1 = b_out[nh * 128 + col + 1];
        scr[(wid * 16 + g) * SCRP + col]         = gelu_f(c[j][0] + bo0);
        scr[(wid * 16 + g) * SCRP + col + 1]     = gelu_f(c[j][1] + bo1);
        scr[(wid * 16 + g + 8) * SCRP + col]     = gelu_f(c[j][2] + bo0);
        scr[(wid * 16 + g + 8) * SCRP + col + 1] = gelu_f(c[j][3] + bo1);
    }
    __syncthreads();
    if (t < 128) {
        const int cc = t;
        const int row_base = (is_sq ? mt : (mt - NSQT)) * 128;
        const float scale = is_sq ? (1.0f / 64.0f) : (1.0f / 24.0f);
        int cur = is_sq ? (row_base >> 6) : (row_base / 24);
        float acc = 0.f;
        for (int rr = 0; rr < 128; rr++) {
            int gr = row_base + rr;
            int nbd = is_sq ? (gr >> 6) : (gr / 24);
            if (nbd != cur) {
                atomicAdd(&g_shared[cur * DDIM + nh * 128 + cc], acc * scale);
                acc = 0.f; cur = nbd;
            }
            acc += scr[rr * SCRP + cc];
        }
        atomicAdd(&g_shared[cur * DDIM + nh * 128 + cc], acc * scale);
    }
}

// ============================================================================
// heads: pt/vt = gelu(shared @ W + b)
// ============================================================================
#define SMEM2_BYTES ((4096 + 32768) * 4)
__global__ void __launch_bounds__(256) heads_kernel(
    const float* __restrict__ W_pt, const float* __restrict__ b_pt,
    const float* __restrict__ W_vt, const float* __restrict__ b_vt)
{
    extern __shared__ float sm[];
    float* At = sm;
    float* Bt = sm + 4096;
    const int t = threadIdx.x;
    const int r0 = blockIdx.x * 16;
    for (int i = t; i < 16 * 256; i += 256) At[i] = g_shared[r0 * 256 + i];
    const int c4 = (t & 31) * 4;
    const int rg = t >> 5;
    #pragma unroll
    for (int w = 0; w < 2; w++) {
        __syncthreads();
        const float* W  = w ? W_vt : W_pt;
        const float* bb = w ? b_vt : b_pt;
        float* outp     = w ? g_vt : g_pt;
        for (int i = t; i < 256 * 128; i += 256) Bt[i] = W[i];
        __syncthreads();
        float C[2][4] = {{0.f, 0.f, 0.f, 0.f}, {0.f, 0.f, 0.f, 0.f}};
        #pragma unroll 2
        for (int k = 0; k < 256; k += 4) {
            float4 a0 = *(const float4*)&At[(rg * 2) * 256 + k];
            float4 a1 = *(const float4*)&At[(rg * 2 + 1) * 256 + k];
            #pragma unroll
            for (int kk = 0; kk < 4; kk++) {
                float4 bv = *(const float4*)&Bt[(k + kk) * 128 + c4];
                float v0 = sel4(a0, kk), v1 = sel4(a1, kk);
                C[0][0] += v0 * bv.x; C[0][1] += v0 * bv.y; C[0][2] += v0 * bv.z; C[0][3] += v0 * bv.w;
                C[1][0] += v1 * bv.x; C[1][1] += v1 * bv.y; C[1][2] += v1 * bv.z; C[1][3] += v1 * bv.w;
            }
        }
        #pragma unroll
        for (int i = 0; i < 2; i++) {
            int r = r0 + rg * 2 + i;
            float4 o;
            o.x = gelu_f(C[i][0] + bb[c4 + 0]);
            o.y = gelu_f(C[i][1] + bb[c4 + 1]);
            o.z = gelu_f(C[i][2] + bb[c4 + 2]);
            o.w = gelu_f(C[i][3] + bb[c4 + 3]);
            *(float4*)&outp[r * 128 + c4] = o;
        }
    }
}

// ============================================================================
// policy: out = pt @ W_ph + b_ph via HMMA 3-pass. grid (37, 16).
// ============================================================================
__global__ void __launch_bounds__(256, 1) policy_kernel(
    const float* __restrict__ b_ph, float* __restrict__ out)
{
    extern __shared__ uint8_t smraw[];
    __nv_bfloat16* Ahi = (__nv_bfloat16*)(smraw);
    __nv_bfloat16* Alo = (__nv_bfloat16*)(smraw + TILEB);
    __nv_bfloat16* Bhi = (__nv_bfloat16*)(smraw + 2 * TILEB);
    __nv_bfloat16* Blo = (__nv_bfloat16*)(smraw + 3 * TILEB);
    const int t = threadIdx.x;
    const int lane = t & 31, wid = t >> 5;
    const int g = lane >> 2, tg = lane & 3;
    const int nt = blockIdx.x;
    const int mtl = blockIdx.y;

    {
        const uint32_t* sH = (const uint32_t*)(g_Wph + (size_t)nt * 16384);
        const uint32_t* sL = (const uint32_t*)(g_Wph + (size_t)APAD * 128 + (size_t)nt * 16384);
        stage_Bptr(Bhi, Blo, sH, sL, t);
    }
    stage_Asrc(Ahi, Alo, g_pt + (size_t)mtl * 16384, t);
    __syncthreads();

    float c[16][4];
    #pragma unroll
    for (int j = 0; j < 16; j++)
        #pragma unroll
        for (int q = 0; q < 4; q++) c[j][q] = 0.f;
    mma_3pass(c, Ahi, Alo, Bhi, Blo, wid, g, tg);

    #pragma unroll
    for (int j = 0; j < 16; j++) {
        int colg = nt * 128 + j * 8 + tg * 2;
        if (colg < ADIM) {
            float2 bp = *(const float2*)&b_ph[colg];
            int r0 = mtl * 128 + wid * 16 + g;
            *(float2*)&out[(size_t)r0 * ADIM + colg] =
                make_float2(c[j][0] + bp.x, c[j][1] + bp.y);
            *(float2*)&out[(size_t)(r0 + 8) * ADIM + colg] =
                make_float2(c[j][2] + bp.x, c[j][3] + bp.y);
        }
    }
}

__global__ void __launch_bounds__(256) value_kernel(
    const float* __restrict__ W_vh, const float* __restrict__ b_vh,
    float* __restrict__ out)
{
    int r = blockIdx.x * 8 + (threadIdx.x >> 5);
    int lane = threadIdx.x & 31;
    float acc = 0.f;
    #pragma unroll
    for (int q = 0; q < 4; q++)
        acc += g_vt[r * 128 + q * 32 + lane] * W_vh[q * 32 + lane];
    #pragma unroll
    for (int o = 16; o; o >>= 1) acc += __shfl_xor_sync(0xffffffffu, acc, o);
    if (lane == 0) out[(size_t)NB * ADIM + r] = tanhf(acc + b_vh[0]);
}

extern "C" void kernel_launch(void* const* d_in, const int* in_sizes, int n_in,
                              void* d_out, int out_size) {
    (void)in_sizes; (void)n_in; (void)out_size;
    const float* x_sq    = (const float*)d_in[0];
    const float* x_pc    = (const float*)d_in[1];
    const float* W_in_sq = (const float*)d_in[2];
    const float* b_in_sq = (const float*)d_in[3];
    const float* W_in_pc = (const float*)d_in[4];
    const float* b_in_pc = (const float*)d_in[5];
    const float* W_adj   = (const float*)d_in[6];
    const float* W_occ   = (const float*)d_in[7];
    const float* W_att   = (const float*)d_in[8];
    const float* W_def   = (const float*)d_in[9];
    const float* W_rev   = (const float*)d_in[10];
    const float* W_out   = (const float*)d_in[11];
    const float* b_out   = (const float*)d_in[12];
    const float* W_pt    = (const float*)d_in[13];
    const float* b_pt    = (const float*)d_in[14];
    const float* W_vt    = (const float*)d_in[15];
    const float* b_vt    = (const float*)d_in[16];
    const float* W_ph    = (const float*)d_in[17];
    const float* b_ph    = (const float*)d_in[18];
    const float* W_vh    = (const float*)d_in[19];
    const float* b_vh    = (const float*)d_in[20];
    const int* ei_adj    = (const int*)d_in[21];
    const int* ei_occ    = (const int*)d_in[22];
    const int* ei_att    = (const int*)d_in[23];
    const int* ei_def    = (const int*)d_in[24];
    const int* ei_rev    = (const int*)d_in[25];
    float* out = (float*)d_out;

    cudaFuncSetAttribute(stage1_kernel,  cudaFuncAttributeMaxDynamicSharedMemorySize, S1_BYTES);
    cudaFuncSetAttribute(gemmA_kernel,   cudaFuncAttributeMaxDynamicSharedMemorySize, TILE_SMEM);
    cudaFuncSetAttribute(outgemm_kernel, cudaFuncAttributeMaxDynamicSharedMemorySize, TILE_SMEM);
    cudaFuncSetAttribute(policy_kernel,  cudaFuncAttributeMaxDynamicSharedMemorySize, TILE_SMEM);
    cudaFuncSetAttribute(heads_kernel,   cudaFuncAttributeMaxDynamicSharedMemorySize, SMEM2_BYTES);

    prep_kernel<<<128, 256>>>(W_adj, W_occ, W_att, W_def, W_rev, W_out, W_ph);

    stage1_kernel<<<NB, T512, S1_BYTES>>>(
        x_sq, x_pc, W_in_sq, b_in_sq, W_in_pc, b_in_pc,
        ei_adj, ei_att, ei_def, ei_rev);

    gemmA_kernel<<<NSQT + 2 * NPCT, 256, TILE_SMEM>>>();

    stage2_kernel<<<NB, T512>>>(ei_occ);

    outgemm_kernel<<<(NSQT + NPCT) * 2, 256, TILE_SMEM>>>(b_out);

    heads_kernel<<<NB / 16, 256, SMEM2_BYTES>>>(W_pt, b_pt, W_vt, b_vt);

    policy_kernel<<<dim3(37, 16), 256, TILE_SMEM>>>(b_ph, out);

    value_kernel<<<NB / 8, 256>>>(W_vh, b_vh, out);
}